// round 14
// baseline (speedup 1.0000x reference)
#include <cuda_runtime.h>
#include <cuda_bf16.h>
#include <cfloat>
#include <cstddef>
#include <cstdint>

#define NN 4096
#define CC 256
#define VV 4
#define NP 6
#define SIMSZ ((size_t)NN * NN)

// ---------------- scratch (per-pair axes) ----------------
__device__ __nv_bfloat16 g_dnb_h[VV * NN * CC];
__device__ __nv_bfloat16 g_dnb_r[VV * NN * CC];
__device__ __nv_bfloat16 g_sfT_h[VV * CC * NN];
__device__ __nv_bfloat16 g_wrT_h[CC * CC];
__device__ __nv_bfloat16 g_wrT_r[CC * CC];
__device__ float g_recon[VV * NN * CC];
__device__ float g_relWT[12 * CC];
__device__ __nv_bfloat16 g_simb[NP * SIMSZ];
__device__ __nv_bfloat16 g_p_h[NP * SIMSZ];
__device__ __nv_bfloat16 g_pT_h[NP * SIMSZ];

__device__ float g_rowmax_part[NP * 32 * NN];
__device__ int   g_rowidx_part[NP * 32 * NN];
__device__ float g_colmax_part[NP * 32 * NN];
__device__ int   g_colidx_part[NP * 32 * NN];
__device__ float g_rowmax[NP * NN];
__device__ int   g_rowidx[NP * NN];
__device__ float g_colmax[NP * NN];
__device__ int   g_colidx[NP * NN];
__device__ float g_rowsum[NP * NN];
__device__ float g_colsum[NP * NN];
__device__ int   g_rowlist[NP * NN];
__device__ int   g_collist[NP * NN];
__device__ int   g_nsel[NP * 2];

__device__ float g_sprow[(size_t)NP * NN * 64];
__device__ float g_spcol[(size_t)NP * NN * 64];

__device__ float g_soft_row[NP * NN * CC];
__device__ float g_soft_col[NP * NN * CC];
__device__ float g_sq_part[12 * 32];
__device__ int   g_cnt_part[12 * 32];

__constant__ int c_OPI[12] = {0,0,0,1,1,1,2,2,2,3,3,3};
__constant__ int c_OPJ[12] = {1,2,3,0,2,3,0,1,3,0,1,2};
__constant__ int c_PI[NP]  = {0,0,0,1,1,2};
__constant__ int c_PJ[NP]  = {1,2,3,2,3,3};
__constant__ int c_OP0[NP] = {0,1,2,4,5,8};
__constant__ int c_OP1[NP] = {3,6,9,7,10,11};

// ---------------- helpers ----------------
__device__ __forceinline__ uint32_t smem_u32(const void* p) {
    uint32_t a;
    asm("{ .reg .u64 t; cvta.to.shared.u64 t, %1; cvt.u32.u64 %0, t; }" : "=r"(a) : "l"(p));
    return a;
}
__device__ __forceinline__ uint32_t swz64(int row, int kc) {
    return (uint32_t)(row * 64) + (uint32_t)(((kc ^ ((row >> 1) & 3)) & 3) << 4);
}
__device__ __forceinline__ void ldm_x4(uint32_t addr, uint32_t& r0, uint32_t& r1,
                                       uint32_t& r2, uint32_t& r3) {
    asm volatile("ldmatrix.sync.aligned.m8n8.x4.shared.b16 {%0,%1,%2,%3}, [%4];"
        : "=r"(r0), "=r"(r1), "=r"(r2), "=r"(r3) : "r"(addr));
}
__device__ __forceinline__ void mma_bf16(float* c, const uint32_t* a, uint32_t b0, uint32_t b1) {
    asm volatile("mma.sync.aligned.m16n8k16.row.col.f32.bf16.bf16.f32 "
        "{%0,%1,%2,%3}, {%4,%5,%6,%7}, {%8,%9}, {%0,%1,%2,%3};"
        : "+f"(c[0]), "+f"(c[1]), "+f"(c[2]), "+f"(c[3])
        : "r"(a[0]), "r"(a[1]), "r"(a[2]), "r"(a[3]), "r"(b0), "r"(b1));
}
__device__ __forceinline__ float fast_exp(float x) {
    float y = x * 1.4426950408889634f;
    float n = rintf(y);
    float f = y - n;
    float r = 0.0001540353039338f;
    r = r * f + 0.0013333558146428f;
    r = r * f + 0.0096181291076285f;
    r = r * f + 0.0555041086648216f;
    r = r * f + 0.2402265069591007f;
    r = r * f + 0.6931471805599453f;
    r = r * f + 1.0f;
    return __int_as_float(__float_as_int(r) + ((int)n << 23));
}

// 32x64-warp-tile MMA over a 32-K smem block (recon / weighted gemm)
__device__ __forceinline__ void mma_block(uint32_t sA, uint32_t sB, int lane,
                                          int m0w, int n0w, float acc[2][8][4]) {
    const int arow = m0w + (lane & 7) + ((lane >> 3) & 1) * 8;
    const int akc  = lane >> 4;
    const int brow = n0w + (lane & 7) + (lane >> 4) * 8;
    const int bkc  = (lane >> 3) & 1;
    #pragma unroll
    for (int ks = 0; ks < 2; ks++) {
        uint32_t a[2][4];
        #pragma unroll
        for (int mt = 0; mt < 2; mt++)
            ldm_x4(sA + swz64(arow + mt * 16, ks * 2 + akc),
                   a[mt][0], a[mt][1], a[mt][2], a[mt][3]);
        #pragma unroll
        for (int np = 0; np < 4; np++) {
            uint32_t b0, b1, b2, b3;
            ldm_x4(sB + swz64(brow + np * 16, ks * 2 + bkc), b0, b1, b2, b3);
            #pragma unroll
            for (int mt = 0; mt < 2; mt++) {
                mma_bf16(acc[mt][np * 2],     a[mt], b0, b1);
                mma_bf16(acc[mt][np * 2 + 1], a[mt], b2, b3);
            }
        }
    }
}

// 64x64-warp-tile MMA over a 32-K smem block (sim)
__device__ __forceinline__ void mma_block_w(uint32_t sA, uint32_t sB, int lane,
                                            int m0w, int n0w, float acc[4][8][4]) {
    const int arow = m0w + (lane & 7) + ((lane >> 3) & 1) * 8;
    const int akc  = lane >> 4;
    const int brow = n0w + (lane & 7) + (lane >> 4) * 8;
    const int bkc  = (lane >> 3) & 1;
    #pragma unroll
    for (int ks = 0; ks < 2; ks++) {
        uint32_t a[4][4];
        #pragma unroll
        for (int mt = 0; mt < 4; mt++)
            ldm_x4(sA + swz64(arow + mt * 16, ks * 2 + akc),
                   a[mt][0], a[mt][1], a[mt][2], a[mt][3]);
        #pragma unroll
        for (int nb = 0; nb < 4; nb++) {
            uint32_t b0, b1, b2, b3;
            ldm_x4(sB + swz64(brow + nb * 16, ks * 2 + bkc), b0, b1, b2, b3);
            #pragma unroll
            for (int mt = 0; mt < 4; mt++) {
                mma_bf16(acc[mt][nb * 2],     a[mt], b0, b1);
                mma_bf16(acc[mt][nb * 2 + 1], a[mt], b2, b3);
            }
        }
    }
}

// ---------------- fused setup: normalize | sf transpose | wr transpose | relWT ---
#define NORM_N (NN * VV)
#define SF_N   ((NN / 32) * (CC / 32) * VV)
#define WR_N   64
__global__ void __launch_bounds__(256) setup_kernel(
    const float* __restrict__ desc, const float* __restrict__ sf,
    const float* __restrict__ W, const float* __restrict__ T,
    const float* __restrict__ WT)
{
    __shared__ float ss[256];
    __shared__ float tt[32][33];
    int b = blockIdx.x;
    int tid = threadIdx.x;
    if (b < NORM_N) {
        int rv = b;
        float x = desc[(size_t)rv * CC + tid];
        ss[tid] = x * x;
        __syncthreads();
        for (int off = 128; off > 0; off >>= 1) {
            if (tid < off) ss[tid] += ss[tid + off];
            __syncthreads();
        }
        float den = fmaxf(sqrtf(ss[0]), 1e-12f);
        float y = x / den;
        int n = rv / VV, v = rv % VV;
        __nv_bfloat16 h = __float2bfloat16_rn(y);
        size_t off = (size_t)(v * NN + n) * CC + tid;
        g_dnb_h[off] = h;
        g_dnb_r[off] = __float2bfloat16_rn(y - __bfloat162float(h));
        return;
    }
    b -= NORM_N;
    if (b < SF_N) {
        int v = b >> 10;
        int rem = b & 1023;
        int n0 = (rem & 127) * 32;
        int c0 = (rem >> 7) * 32;
        int tx = tid & 31, ty = tid >> 5;
        #pragma unroll
        for (int q = 0; q < 4; q++) {
            int r = ty * 4 + q;
            tt[r][tx] = sf[(size_t)(n0 + r) * (VV * CC) + v * CC + c0 + tx];
        }
        __syncthreads();
        #pragma unroll
        for (int q = 0; q < 4; q++) {
            int r = ty * 4 + q;
            g_sfT_h[(size_t)v * CC * NN + (size_t)(c0 + r) * NN + n0 + tx] =
                __float2bfloat16_rn(tt[tx][r]);
        }
        return;
    }
    b -= SF_N;
    if (b < WR_N) {
        int c0 = (b & 7) * 32;
        int k0 = (b >> 3) * 32;
        int tx = tid & 31, ty = tid >> 5;
        #pragma unroll
        for (int q = 0; q < 4; q++) {
            int r = ty * 4 + q;
            tt[r][tx] = W[(size_t)(k0 + r) * CC + c0 + tx];
        }
        __syncthreads();
        #pragma unroll
        for (int q = 0; q < 4; q++) {
            int r = ty * 4 + q;
            float x = tt[tx][r];
            __nv_bfloat16 h = __float2bfloat16_rn(x);
            size_t off = (size_t)(c0 + r) * CC + k0 + tx;
            g_wrT_h[off] = h;
            g_wrT_r[off] = __float2bfloat16_rn(x - __bfloat162float(h));
        }
        return;
    }
    b -= WR_N;
    {
        int op = b;
        int c = tid;
        int i = c_OPI[op], j = c_OPJ[op];
        float s = 0.0f;
        #pragma unroll
        for (int k = 0; k < 16; k++) s += T[i * 16 + k] * WT[k * CC + c];
        #pragma unroll
        for (int k = 0; k < 16; k++) s += T[j * 16 + k] * WT[(16 + k) * CC + c];
        g_relWT[op * CC + c] = s;
    }
}

// ---------------- recon bf16 MMA (3-term), grid (2, 32, VV) ----------------
__global__ void __launch_bounds__(256) recon_mma_kernel() {
    __shared__ __align__(16) char sm[2][16384];
    const int t = threadIdx.x;
    const int lane = t & 31, wid = t >> 5;
    const int m0w = (wid & 3) * 32, n0w = (wid >> 2) * 64;
    const int v = blockIdx.z;
    const int m0 = blockIdx.y * 128, n0 = blockIdx.x * 128;
    const int lrow = t >> 2, q = t & 3;
    const uint32_t sbase = smem_u32(&sm[0][0]);
    const __nv_bfloat16* Ah = g_dnb_h + (size_t)v * NN * CC;
    const __nv_bfloat16* Ar = g_dnb_r + (size_t)v * NN * CC;

    float acc[2][8][4];
    #pragma unroll
    for (int a = 0; a < 2; a++)
        #pragma unroll
        for (int b = 0; b < 8; b++)
            #pragma unroll
            for (int c = 0; c < 4; c++) acc[a][b][c] = 0.0f;

    uint4 ra0, ra1, rb0, rb1;
    #define R_LDG(KB) do { \
        int seg = (KB) >> 3; \
        int kk = ((KB) & 7) << 5; \
        const __nv_bfloat16* ap = (seg == 2) ? Ar : Ah; \
        const __nv_bfloat16* bp = (seg == 1) ? g_wrT_r : g_wrT_h; \
        ra0 = *(const uint4*)(ap + (size_t)(m0 + lrow) * CC + kk + q * 8); \
        ra1 = *(const uint4*)(ap + (size_t)(m0 + lrow + 64) * CC + kk + q * 8); \
        rb0 = *(const uint4*)(bp + (size_t)(n0 + lrow) * CC + kk + q * 8); \
        rb1 = *(const uint4*)(bp + (size_t)(n0 + lrow + 64) * CC + kk + q * 8); \
    } while (0)
    #define R_STS(BUF) do { \
        char* base = &sm[BUF][0]; \
        *(uint4*)(base + swz64(lrow, q)) = ra0; \
        *(uint4*)(base + swz64(lrow + 64, q)) = ra1; \
        *(uint4*)(base + 8192 + swz64(lrow, q)) = rb0; \
        *(uint4*)(base + 8192 + swz64(lrow + 64, q)) = rb1; \
    } while (0)

    R_LDG(0);
    R_STS(0);
    __syncthreads();
    for (int kb = 0; kb < 24; kb++) {
        int buf = kb & 1;
        if (kb + 1 < 24) R_LDG(kb + 1);
        mma_block(sbase + buf * 16384, sbase + buf * 16384 + 8192, lane, m0w, n0w, acc);
        if (kb + 1 < 24) R_STS(buf ^ 1);
        __syncthreads();
    }
    #undef R_LDG
    #undef R_STS

    const int gid = lane >> 2, tig = lane & 3;
    float* C = g_recon + (size_t)v * NN * CC;
    #pragma unroll
    for (int mt = 0; mt < 2; mt++) {
        int r0 = m0 + m0w + mt * 16 + gid;
        #pragma unroll
        for (int np = 0; np < 8; np++) {
            int c = n0 + n0w + np * 8 + tig * 2;
            *(float2*)&C[(size_t)r0 * CC + c] = make_float2(acc[mt][np][0], acc[mt][np][1]);
            *(float2*)&C[(size_t)(r0 + 8) * CC + c] = make_float2(acc[mt][np][2], acc[mt][np][3]);
        }
    }
}

// ---------------- sim bf16 MMA (3-term), 4 warps x 64x64 tiles: grid (32,32,NP) --
__global__ void __launch_bounds__(128, 2) sim_all_kernel() {
    __shared__ __align__(16) union {
        char bufs[2][16384];
        struct {
            float rv[2][128]; int ri[2][128];
            float cv[2][128]; int ci[2][128];
        } ep;
    } sh;

    const int t = threadIdx.x;
    const int lane = t & 31, wid = t >> 5;
    const int m0w = (wid & 1) * 64, n0w = (wid >> 1) * 64;
    const int p = blockIdx.z;
    const int m0 = blockIdx.y * 128, col0 = blockIdx.x * 128;
    const uint32_t sbase = smem_u32(&sh.bufs[0][0]);

    const __nv_bfloat16* Ah = g_dnb_h + (size_t)c_PI[p] * NN * CC;
    const __nv_bfloat16* Ar = g_dnb_r + (size_t)c_PI[p] * NN * CC;
    const __nv_bfloat16* Bh = g_dnb_h + (size_t)c_PJ[p] * NN * CC;
    const __nv_bfloat16* Br = g_dnb_r + (size_t)c_PJ[p] * NN * CC;
    __nv_bfloat16* simp = g_simb + (size_t)p * SIMSZ;

    float acc[4][8][4];
    #pragma unroll
    for (int a = 0; a < 4; a++)
        #pragma unroll
        for (int b = 0; b < 8; b++)
            #pragma unroll
            for (int c = 0; c < 4; c++) acc[a][b][c] = 0.0f;

    uint4 ra[4], rb[4];
    // terms: 0: h*h, 1: h*r, 2: r*h  (rr dropped)
    #define SIM_LDG(KB) do { \
        int seg = (KB) >> 3; \
        int kk = ((KB) & 7) << 5; \
        const __nv_bfloat16* ap = (seg == 2) ? Ar : Ah; \
        const __nv_bfloat16* bp = (seg == 1) ? Br : Bh; \
        const uint4* ag = (const uint4*)(ap + (size_t)(m0 + t) * CC + kk); \
        const uint4* bg = (const uint4*)(bp + (size_t)(col0 + t) * CC + kk); \
        ra[0] = ag[0]; ra[1] = ag[1]; ra[2] = ag[2]; ra[3] = ag[3]; \
        rb[0] = bg[0]; rb[1] = bg[1]; rb[2] = bg[2]; rb[3] = bg[3]; \
    } while (0)
    #define SIM_STS(BUF) do { \
        char* base = &sh.bufs[BUF][0]; \
        _Pragma("unroll") \
        for (int qq = 0; qq < 4; qq++) { \
            *(uint4*)(base + swz64(t, qq)) = ra[qq]; \
            *(uint4*)(base + 8192 + swz64(t, qq)) = rb[qq]; \
        } \
    } while (0)

    SIM_LDG(0);
    SIM_STS(0);
    __syncthreads();
    for (int kb = 0; kb < 24; kb++) {
        int buf = kb & 1;
        if (kb + 1 < 24) SIM_LDG(kb + 1);
        mma_block_w(sbase + buf * 16384, sbase + buf * 16384 + 8192, lane, m0w, n0w, acc);
        if (kb + 1 < 24) SIM_STS(buf ^ 1);
        __syncthreads();
    }
    #undef SIM_LDG
    #undef SIM_STS

    const int gid = lane >> 2, tig = lane & 3;
    // write sim bf16 (mask decisions use fp32 accs)
    #pragma unroll
    for (int mt = 0; mt < 4; mt++) {
        int r0 = m0 + m0w + mt * 16 + gid;
        #pragma unroll
        for (int np = 0; np < 8; np++) {
            int c = col0 + n0w + np * 8 + tig * 2;
            __nv_bfloat162 lo = __float22bfloat162_rn(make_float2(acc[mt][np][0], acc[mt][np][1]));
            __nv_bfloat162 hi = __float22bfloat162_rn(make_float2(acc[mt][np][2], acc[mt][np][3]));
            *(__nv_bfloat162*)&simp[(size_t)r0 * NN + c] = lo;
            *(__nv_bfloat162*)&simp[(size_t)(r0 + 8) * NN + c] = hi;
        }
    }
    // row-max partials: n-group = wid>>1 (cols [0,64) then [64,128) ascending)
    #pragma unroll
    for (int mt = 0; mt < 4; mt++)
        #pragma unroll
        for (int h = 0; h < 2; h++) {
            float bv = -FLT_MAX; int bi = 0;
            #pragma unroll
            for (int np = 0; np < 8; np++)
                #pragma unroll
                for (int e = 0; e < 2; e++) {
                    float v = acc[mt][np][h * 2 + e];
                    int c = col0 + n0w + np * 8 + tig * 2 + e;
                    if (v > bv) { bv = v; bi = c; }
                }
            #pragma unroll
            for (int o = 1; o <= 2; o <<= 1) {
                float v2 = __shfl_xor_sync(0xffffffffu, bv, o);
                int i2 = __shfl_xor_sync(0xffffffffu, bi, o);
                if (v2 > bv || (v2 == bv && i2 < bi)) { bv = v2; bi = i2; }
            }
            if (tig == 0) {
                int rl = m0w + mt * 16 + h * 8 + gid;
                sh.ep.rv[wid >> 1][rl] = bv;
                sh.ep.ri[wid >> 1][rl] = bi;
            }
        }
    // col-max partials: m-group = wid&1 (rows [0,64) then [64,128) ascending)
    #pragma unroll
    for (int np = 0; np < 8; np++)
        #pragma unroll
        for (int e = 0; e < 2; e++) {
            float bv = -FLT_MAX; int bi = 0;
            #pragma unroll
            for (int mt = 0; mt < 4; mt++)
                #pragma unroll
                for (int h = 0; h < 2; h++) {
                    float v = acc[mt][np][h * 2 + e];
                    int r = m0 + m0w + mt * 16 + h * 8 + gid;
                    if (v > bv) { bv = v; bi = r; }
                }
            #pragma unroll
            for (int o = 4; o <= 16; o <<= 1) {
                float v2 = __shfl_xor_sync(0xffffffffu, bv, o);
                int i2 = __shfl_xor_sync(0xffffffffu, bi, o);
                if (v2 > bv || (v2 == bv && i2 < bi)) { bv = v2; bi = i2; }
            }
            if (gid == 0) {
                int cl = n0w + np * 8 + tig * 2 + e;
                sh.ep.cv[wid & 1][cl] = bv;
                sh.ep.ci[wid & 1][cl] = bi;
            }
        }
    __syncthreads();
    {
        float bv = sh.ep.rv[0][t]; int bi = sh.ep.ri[0][t];
        if (sh.ep.rv[1][t] > bv || (sh.ep.rv[1][t] == bv && sh.ep.ri[1][t] < bi)) {
            bv = sh.ep.rv[1][t]; bi = sh.ep.ri[1][t];
        }
        g_rowmax_part[(size_t)p * 32 * NN + blockIdx.x * NN + m0 + t] = bv;
        g_rowidx_part[(size_t)p * 32 * NN + blockIdx.x * NN + m0 + t] = bi;
        float cv = sh.ep.cv[0][t]; int ci = sh.ep.ci[0][t];
        if (sh.ep.cv[1][t] > cv || (sh.ep.cv[1][t] == cv && sh.ep.ci[1][t] < ci)) {
            cv = sh.ep.cv[1][t]; ci = sh.ep.ci[1][t];
        }
        g_colmax_part[(size_t)p * 32 * NN + blockIdx.y * NN + col0 + t] = cv;
        g_colidx_part[(size_t)p * 32 * NN + blockIdx.y * NN + col0 + t] = ci;
    }
}

// ---------------- max reduce, all pairs: grid (16, NP) ----------------
__global__ void __launch_bounds__(256) maxreduce_all_kernel() {
    int p = blockIdx.y;
    int n = blockIdx.x * 256 + threadIdx.x;
    size_t pb = (size_t)p * 32 * NN;
    float bm = g_rowmax_part[pb + n]; int bi = g_rowidx_part[pb + n];
    for (int s = 1; s < 32; s++) {
        float v = g_rowmax_part[pb + s * NN + n];
        int i2 = g_rowidx_part[pb + s * NN + n];
        if (v > bm || (v == bm && i2 < bi)) { bm = v; bi = i2; }
    }
    g_rowmax[p * NN + n] = bm; g_rowidx[p * NN + n] = bi;
    bm = g_colmax_part[pb + n]; bi = g_colidx_part[pb + n];
    for (int s = 1; s < 32; s++) {
        float v = g_colmax_part[pb + s * NN + n];
        int i2 = g_colidx_part[pb + s * NN + n];
        if (v > bm || (v == bm && i2 < bi)) { bm = v; bi = i2; }
    }
    g_colmax[p * NN + n] = bm; g_colidx[p * NN + n] = bi;
}

// ---------------- compaction, all pairs: grid NP ----------------
__global__ void __launch_bounds__(1024) compact_all_kernel() {
    __shared__ int tsum[1024];
    int p = blockIdx.x;
    const int* ridx = g_rowidx + p * NN;
    const int* cidx = g_colidx + p * NN;
    int* rlist = g_rowlist + p * NN;
    int* clist = g_collist + p * NN;
    int t = threadIdx.x;
    int flags[8];
    int s = 0;
    #pragma unroll
    for (int u = 0; u < 8; u++) {
        int idx = t * 8 + u;
        int f;
        if (idx < NN) { int n = idx; f = (cidx[ridx[n]] == n); }
        else          { int m = idx - NN; f = (ridx[cidx[m]] == m); }
        flags[u] = f;
        s += f;
    }
    tsum[t] = s;
    __syncthreads();
    for (int off = 1; off < 1024; off <<= 1) {
        int v = (t >= off) ? tsum[t - off] : 0;
        __syncthreads();
        tsum[t] += v;
        __syncthreads();
    }
    int rowtot = tsum[511];
    int total = tsum[1023];
    if (t == 0) { g_nsel[p * 2] = rowtot; g_nsel[p * 2 + 1] = total - rowtot; }
    int run = (t > 0) ? tsum[t - 1] : 0;
    #pragma unroll
    for (int u = 0; u < 8; u++) {
        if (flags[u]) {
            int idx = t * 8 + u;
            if (idx < NN) rlist[run] = idx;
            else          clist[run - rowtot] = idx - NN;
            run++;
        }
    }
    __syncthreads();
    int coltot = total - rowtot;
    for (int i2 = rowtot + t; i2 < NN; i2 += 1024) rlist[i2] = 0;
    for (int i2 = coltot + t; i2 < NN; i2 += 1024) clist[i2] = 0;
}

// ---------------- fused exp + sum partials: grid (64, 64, NP) -------------------
__global__ void __launch_bounds__(256) exp_all_kernel() {
    __shared__ float tile[64][65];
    __shared__ int rflag[64], cflag[64];
    __shared__ int s_any;
    const int p = blockIdx.z;
    const int m0 = blockIdx.x * 64;
    const int k0 = blockIdx.y * 64;
    const int t = threadIdx.x;
    const int l = t & 31;
    const int* ridx = g_rowidx + p * NN;
    const int* cidx = g_colidx + p * NN;
    if (t == 0) s_any = 0;
    __syncthreads();
    if (t < 64) {
        int k = k0 + t;
        int f = (cidx[ridx[k]] == k);
        rflag[t] = f;
        if (__ballot_sync(0xffffffffu, f) && l == 0) atomicOr(&s_any, 1);
    } else if (t < 128) {
        int m = m0 + t - 64;
        int f = (ridx[cidx[m]] == m);
        cflag[t - 64] = f;
        if (__ballot_sync(0xffffffffu, f) && l == 0) atomicOr(&s_any, 1);
    }
    __syncthreads();
    if (!s_any) return;

    const int r = (t >> 5) * 8 + (l >> 2);
    const int c0 = (l & 3) * 16;
    const __nv_bfloat16* simp = g_simb + (size_t)p * SIMSZ;

    float fv[16];
    {
        uint4 va = *(const uint4*)(simp + (size_t)(k0 + r) * NN + m0 + c0);
        uint4 vb = *(const uint4*)(simp + (size_t)(k0 + r) * NN + m0 + c0 + 8);
        const uint32_t* ua = (const uint32_t*)&va;
        const uint32_t* ub = (const uint32_t*)&vb;
        #pragma unroll
        for (int i = 0; i < 4; i++) {
            float2 f2 = __bfloat1622float2(*(const __nv_bfloat162*)&ua[i]);
            fv[2 * i] = f2.x; fv[2 * i + 1] = f2.y;
        }
        #pragma unroll
        for (int i = 0; i < 4; i++) {
            float2 f2 = __bfloat1622float2(*(const __nv_bfloat162*)&ub[i]);
            fv[8 + 2 * i] = f2.x; fv[9 + 2 * i] = f2.y;
        }
    }
    #pragma unroll
    for (int i = 0; i < 16; i++) tile[r][c0 + i] = fv[i];

    float s = 0.0f;
    uint32_t out[8];
    const bool fr = rflag[r];
    if (fr) {
        float rm = g_rowmax[p * NN + k0 + r];
        #pragma unroll
        for (int i = 0; i < 8; i++) {
            float e0 = fast_exp(fv[2 * i] - rm);
            float e1 = fast_exp(fv[2 * i + 1] - rm);
            s += e0 + e1;
            __nv_bfloat162 b2 = __float22bfloat162_rn(make_float2(e0, e1));
            out[i] = *(uint32_t*)&b2;
        }
    }
    s += __shfl_xor_sync(0xffffffffu, s, 1);
    s += __shfl_xor_sync(0xffffffffu, s, 2);
    if (fr) {
        __nv_bfloat16* dst = g_p_h + (size_t)p * SIMSZ + (size_t)(k0 + r) * NN + m0 + c0;
        *(uint4*)dst = *(uint4*)&out[0];
        *(uint4*)(dst + 8) = *(uint4*)&out[4];
        if ((l & 3) == 0)
            g_sprow[((size_t)p * NN + k0 + r) * 64 + (m0 >> 6)] = s;
    }
    __syncthreads();

    s = 0.0f;
    const bool fc = cflag[r];
    if (fc) {
        float cm = g_colmax[p * NN + m0 + r];
        #pragma unroll
        for (int i = 0; i < 8; i++) {
            float e0 = fast_exp(tile[c0 + 2 * i][r] - cm);
            float e1 = fast_exp(tile[c0 + 2 * i + 1][r] - cm);
            s += e0 + e1;
            __nv_bfloat162 b2 = __float22bfloat162_rn(make_float2(e0, e1));
            out[i] = *(uint32_t*)&b2;
        }
    }
    s += __shfl_xor_sync(0xffffffffu, s, 1);
    s += __shfl_xor_sync(0xffffffffu, s, 2);
    if (fc) {
        __nv_bfloat16* dst = g_pT_h + (size_t)p * SIMSZ + (size_t)(m0 + r) * NN + k0 + c0;
        *(uint4*)dst = *(uint4*)&out[0];
        *(uint4*)(dst + 8) = *(uint4*)&out[4];
        if ((l & 3) == 0)
            g_spcol[((size_t)p * NN + m0 + r) * 64 + (k0 >> 6)] = s;
    }
}

// ---------------- sums: 8 slots per block, grid (NN/8, 2, NP), 256 thr -----------
__global__ void __launch_bounds__(256) sums_all_kernel() {
    int p = blockIdx.z;
    int dir = blockIdx.y;
    int w = threadIdx.x >> 5;
    int b = blockIdx.x * 8 + w;
    if (b >= g_nsel[p * 2 + dir]) return;
    int row = dir ? g_collist[p * NN + b] : g_rowlist[p * NN + b];
    const float* part = (dir ? g_spcol : g_sprow) + ((size_t)p * NN + row) * 64;
    int t = threadIdx.x & 31;
    float s = part[t] + part[t + 32];
    #pragma unroll
    for (int o = 16; o > 0; o >>= 1) s += __shfl_xor_sync(0xffffffffu, s, o);
    if (t == 0) {
        if (dir) g_colsum[p * NN + row] = s;
        else     g_rowsum[p * NN + row] = s;
    }
}

// ---------------- weighted bf16 MMA, 1-term: grid (2, 32, NP*2) ----------------
__global__ void __launch_bounds__(256) gemm_all_kernel() {
    const int p = blockIdx.z >> 1;
    const int dir = blockIdx.z & 1;
    const int m0 = blockIdx.y * 128;
    const int nsel = g_nsel[p * 2 + dir];
    if (m0 >= nsel) return;
    __shared__ __align__(16) char sm[2][16384];

    const int t = threadIdx.x;
    const int lane = t & 31, wid = t >> 5;
    const int m0w = (wid & 3) * 32, n0w = (wid >> 2) * 64;
    const int n0 = blockIdx.x * 128;
    const int lrow = t >> 2, q = t & 3;
    const uint32_t sbase = smem_u32(&sm[0][0]);

    const int* list = (dir ? g_collist : g_rowlist) + p * NN;
    const __nv_bfloat16* Ph = (dir ? g_pT_h : g_p_h) + (size_t)p * SIMSZ;
    const int sv = dir ? c_PI[p] : c_PJ[p];
    const __nv_bfloat16* Sh = g_sfT_h + (size_t)sv * CC * NN;

    const int grow0 = list[m0 + lrow];
    const int grow1 = list[m0 + lrow + 64];

    float acc[2][8][4];
    #pragma unroll
    for (int a = 0; a < 2; a++)
        #pragma unroll
        for (int b = 0; b < 8; b++)
            #pragma unroll
            for (int c = 0; c < 4; c++) acc[a][b][c] = 0.0f;

    uint4 ra0, ra1, rb0, rb1;
    #define W_LDG(KB) do { \
        int kk = (KB) * 32; \
        ra0 = *(const uint4*)(Ph + (size_t)grow0 * NN + kk + q * 8); \
        ra1 = *(const uint4*)(Ph + (size_t)grow1 * NN + kk + q * 8); \
        rb0 = *(const uint4*)(Sh + (size_t)(n0 + lrow) * NN + kk + q * 8); \
        rb1 = *(const uint4*)(Sh + (size_t)(n0 + lrow + 64) * NN + kk + q * 8); \
    } while (0)
    #define W_STS(BUF) do { \
        char* base = &sm[BUF][0]; \
        *(uint4*)(base + swz64(lrow, q)) = ra0; \
        *(uint4*)(base + swz64(lrow + 64, q)) = ra1; \
        *(uint4*)(base + 8192 + swz64(lrow, q)) = rb0; \
        *(uint4*)(base + 8192 + swz64(lrow + 64, q)) = rb1; \
    } while (0)

    W_LDG(0);
    W_STS(0);
    __syncthreads();
    for (int kb = 0; kb < 128; kb++) {
        int buf = kb & 1;
        if (kb + 1 < 128) W_LDG(kb + 1);
        mma_block(sbase + buf * 16384, sbase + buf * 16384 + 8192, lane, m0w, n0w, acc);
        if (kb + 1 < 128) W_STS(buf ^ 1);
        __syncthreads();
    }
    #undef W_LDG
    #undef W_STS

    const int gid = lane >> 2, tig = lane & 3;
    const float* sums = dir ? g_colsum : g_rowsum;
    float* soft = (dir ? g_soft_col : g_soft_row) + (size_t)p * NN * CC;
    #pragma unroll
    for (int mt = 0; mt < 2; mt++) {
        int s0 = m0 + m0w + mt * 16 + gid;
        #pragma unroll
        for (int h = 0; h < 2; h++) {
            int slot = s0 + h * 8;
            if (slot >= nsel) continue;
            int row = list[slot];
            float inv = 1.0f / sums[p * NN + row];
            #pragma unroll
            for (int np = 0; np < 8; np++) {
                int c = n0 + n0w + np * 8 + tig * 2;
                *(float2*)&soft[(size_t)row * CC + c] =
                    make_float2(acc[mt][np][h * 2] * inv, acc[mt][np][h * 2 + 1] * inv);
            }
        }
    }
}

// ---------------- loss (slot-based), all: grid (32, 2, NP) ----------------
__global__ void __launch_bounds__(256) loss_all_kernel() {
    int p = blockIdx.z;
    int dir = blockIdx.y;
    int tid = threadIdx.x;
    int b = blockIdx.x;
    int op = dir ? c_OP1[p] : c_OP0[p];
    int nsel = g_nsel[p * 2 + dir];
    int start = b * 128;
    int cnt = nsel - start;
    if (cnt > 128) cnt = 128;
    if (cnt <= 0) {
        if (tid == 0) { g_sq_part[op * 32 + b] = 0.0f; g_cnt_part[op * 32 + b] = 0; }
        return;
    }
    const int* list = (dir ? g_collist : g_rowlist) + p * NN;
    __shared__ int rows[128];
    if (tid < 128 && tid < cnt) rows[tid] = list[start + tid];
    __syncthreads();
    const float* soft = (dir ? g_soft_col : g_soft_row) + (size_t)p * NN * CC;
    const float* recon = g_recon + (size_t)(dir ? c_PJ[p] : c_PI[p]) * NN * CC;
    float relc = g_relWT[op * CC + tid];
    float lsum = 0.0f;
    for (int i = 0; i < cnt; i++) {
        int row = rows[i];
        float d = recon[(size_t)row * CC + tid] + relc - soft[(size_t)row * CC + tid];
        lsum += d * d;
    }
    __shared__ float ss[256];
    ss[tid] = lsum;
    __syncthreads();
    for (int off = 128; off > 0; off >>= 1) {
        if (tid < off) ss[tid] += ss[tid + off];
        __syncthreads();
    }
    if (tid == 0) {
        g_sq_part[op * 32 + b] = ss[0];
        g_cnt_part[op * 32 + b] = cnt;
    }
}

__global__ void finalize_kernel(float* __restrict__ out) {
    if (threadIdx.x == 0) {
        float total = 0.0f, count = 0.0f;
        for (int op = 0; op < 12; op++) {
            float sq = 0.0f;
            int cnt = 0;
            for (int b = 0; b < 32; b++) {
                sq += g_sq_part[op * 32 + b];
                cnt += g_cnt_part[op * 32 + b];
            }
            if (cnt > 0) {
                total += sq / fmaxf((float)cnt * (float)CC, 1.0f);
                count += 1.0f;
            }
        }
        out[0] = (count > 0.0f) ? (total / fmaxf(count, 1.0f)) : 0.0f;
    }
}

// ---------------- host launch ----------------
extern "C" void kernel_launch(void* const* d_in, const int* in_sizes, int n_in,
                              void* d_out, int out_size)
{
    const float* desc  = (const float*)d_in[0];
    const float* sf    = (const float*)d_in[1];
    const float* T     = (const float*)d_in[2];
    const float* W_rec = (const float*)d_in[3];
    const float* W_T   = (const float*)d_in[4];
    float* out = (float*)d_out;

    setup_kernel<<<NORM_N + SF_N + WR_N + 12, 256>>>(desc, sf, W_rec, T, W_T);
    recon_mma_kernel<<<dim3(2, 32, VV), 256>>>();

    sim_all_kernel<<<dim3(32, 32, NP), 128>>>();
    maxreduce_all_kernel<<<dim3(16, NP), 256>>>();
    compact_all_kernel<<<NP, 1024>>>();
    exp_all_kernel<<<dim3(NN / 64, NN / 64, NP), 256>>>();
    sums_all_kernel<<<dim3(NN / 8, 2, NP), 256>>>();
    gemm_all_kernel<<<dim3(2, 32, NP * 2), 256>>>();
    loss_all_kernel<<<dim3(32, 2, NP), 256>>>();

    finalize_kernel<<<1, 32>>>(out);
}

// round 15
// speedup vs baseline: 1.2870x; 1.2870x over previous
#include <cuda_runtime.h>
#include <cuda_bf16.h>
#include <cfloat>
#include <cstddef>
#include <cstdint>

#define NN 4096
#define CC 256
#define VV 4
#define NP 6
#define SIMSZ ((size_t)NN * NN)

// ---------------- scratch (per-pair axes) ----------------
__device__ __nv_bfloat16 g_dnb_h[VV * NN * CC];
__device__ __nv_bfloat16 g_dnb_r[VV * NN * CC];
__device__ __nv_bfloat16 g_sfT_h[VV * CC * NN];
__device__ __nv_bfloat16 g_wrT_h[CC * CC];
__device__ __nv_bfloat16 g_wrT_r[CC * CC];
__device__ float g_recon[VV * NN * CC];
__device__ float g_relWT[12 * CC];
__device__ __nv_bfloat16 g_simb[NP * SIMSZ];
__device__ __nv_bfloat16 g_p_h[NP * SIMSZ];
__device__ __nv_bfloat16 g_pT_h[NP * SIMSZ];

__device__ float g_rowmax_part[NP * 32 * NN];
__device__ int   g_rowidx_part[NP * 32 * NN];
__device__ float g_colmax_part[NP * 32 * NN];
__device__ int   g_colidx_part[NP * 32 * NN];
__device__ float g_rowmax[NP * NN];
__device__ int   g_rowidx[NP * NN];
__device__ float g_colmax[NP * NN];
__device__ int   g_colidx[NP * NN];
__device__ float g_rowsum[NP * NN];
__device__ float g_colsum[NP * NN];
__device__ int   g_rowlist[NP * NN];
__device__ int   g_collist[NP * NN];
__device__ int   g_nsel[NP * 2];

__device__ float g_sprow[(size_t)NP * NN * 64];
__device__ float g_spcol[(size_t)NP * NN * 64];

__device__ float g_soft_row[NP * NN * CC];
__device__ float g_soft_col[NP * NN * CC];
__device__ float g_sq_part[12 * 32];
__device__ int   g_cnt_part[12 * 32];

__constant__ int c_OPI[12] = {0,0,0,1,1,1,2,2,2,3,3,3};
__constant__ int c_OPJ[12] = {1,2,3,0,2,3,0,1,3,0,1,2};
__constant__ int c_PI[NP]  = {0,0,0,1,1,2};
__constant__ int c_PJ[NP]  = {1,2,3,2,3,3};
__constant__ int c_OP0[NP] = {0,1,2,4,5,8};
__constant__ int c_OP1[NP] = {3,6,9,7,10,11};

// ---------------- helpers ----------------
__device__ __forceinline__ uint32_t smem_u32(const void* p) {
    uint32_t a;
    asm("{ .reg .u64 t; cvta.to.shared.u64 t, %1; cvt.u32.u64 %0, t; }" : "=r"(a) : "l"(p));
    return a;
}
__device__ __forceinline__ uint32_t swz64(int row, int kc) {
    return (uint32_t)(row * 64) + (uint32_t)(((kc ^ ((row >> 1) & 3)) & 3) << 4);
}
__device__ __forceinline__ void ldm_x4(uint32_t addr, uint32_t& r0, uint32_t& r1,
                                       uint32_t& r2, uint32_t& r3) {
    asm volatile("ldmatrix.sync.aligned.m8n8.x4.shared.b16 {%0,%1,%2,%3}, [%4];"
        : "=r"(r0), "=r"(r1), "=r"(r2), "=r"(r3) : "r"(addr));
}
__device__ __forceinline__ void mma_bf16(float* c, const uint32_t* a, uint32_t b0, uint32_t b1) {
    asm volatile("mma.sync.aligned.m16n8k16.row.col.f32.bf16.bf16.f32 "
        "{%0,%1,%2,%3}, {%4,%5,%6,%7}, {%8,%9}, {%0,%1,%2,%3};"
        : "+f"(c[0]), "+f"(c[1]), "+f"(c[2]), "+f"(c[3])
        : "r"(a[0]), "r"(a[1]), "r"(a[2]), "r"(a[3]), "r"(b0), "r"(b1));
}
__device__ __forceinline__ float fast_exp(float x) {
    float y = x * 1.4426950408889634f;
    float n = rintf(y);
    float f = y - n;
    float r = 0.0001540353039338f;
    r = r * f + 0.0013333558146428f;
    r = r * f + 0.0096181291076285f;
    r = r * f + 0.0555041086648216f;
    r = r * f + 0.2402265069591007f;
    r = r * f + 0.6931471805599453f;
    r = r * f + 1.0f;
    return __int_as_float(__float_as_int(r) + ((int)n << 23));
}

__device__ __forceinline__ void mma_block(uint32_t sA, uint32_t sB, int lane,
                                          int m0w, int n0w, float acc[2][8][4]) {
    const int arow = m0w + (lane & 7) + ((lane >> 3) & 1) * 8;
    const int akc  = lane >> 4;
    const int brow = n0w + (lane & 7) + (lane >> 4) * 8;
    const int bkc  = (lane >> 3) & 1;
    #pragma unroll
    for (int ks = 0; ks < 2; ks++) {
        uint32_t a[2][4];
        #pragma unroll
        for (int mt = 0; mt < 2; mt++)
            ldm_x4(sA + swz64(arow + mt * 16, ks * 2 + akc),
                   a[mt][0], a[mt][1], a[mt][2], a[mt][3]);
        #pragma unroll
        for (int np = 0; np < 4; np++) {
            uint32_t b0, b1, b2, b3;
            ldm_x4(sB + swz64(brow + np * 16, ks * 2 + bkc), b0, b1, b2, b3);
            #pragma unroll
            for (int mt = 0; mt < 2; mt++) {
                mma_bf16(acc[mt][np * 2],     a[mt], b0, b1);
                mma_bf16(acc[mt][np * 2 + 1], a[mt], b2, b3);
            }
        }
    }
}

// ---------------- fused setup: normalize | sf transpose | wr transpose | relWT ---
#define NORM_N (NN * VV)
#define SF_N   ((NN / 32) * (CC / 32) * VV)
#define WR_N   64
__global__ void __launch_bounds__(256) setup_kernel(
    const float* __restrict__ desc, const float* __restrict__ sf,
    const float* __restrict__ W, const float* __restrict__ T,
    const float* __restrict__ WT)
{
    __shared__ float ss[256];
    __shared__ float tt[32][33];
    int b = blockIdx.x;
    int tid = threadIdx.x;
    if (b < NORM_N) {
        int rv = b;
        float x = desc[(size_t)rv * CC + tid];
        ss[tid] = x * x;
        __syncthreads();
        for (int off = 128; off > 0; off >>= 1) {
            if (tid < off) ss[tid] += ss[tid + off];
            __syncthreads();
        }
        float den = fmaxf(sqrtf(ss[0]), 1e-12f);
        float y = x / den;
        int n = rv / VV, v = rv % VV;
        __nv_bfloat16 h = __float2bfloat16_rn(y);
        size_t off = (size_t)(v * NN + n) * CC + tid;
        g_dnb_h[off] = h;
        g_dnb_r[off] = __float2bfloat16_rn(y - __bfloat162float(h));
        return;
    }
    b -= NORM_N;
    if (b < SF_N) {
        int v = b >> 10;
        int rem = b & 1023;
        int n0 = (rem & 127) * 32;
        int c0 = (rem >> 7) * 32;
        int tx = tid & 31, ty = tid >> 5;
        #pragma unroll
        for (int q = 0; q < 4; q++) {
            int r = ty * 4 + q;
            tt[r][tx] = sf[(size_t)(n0 + r) * (VV * CC) + v * CC + c0 + tx];
        }
        __syncthreads();
        #pragma unroll
        for (int q = 0; q < 4; q++) {
            int r = ty * 4 + q;
            g_sfT_h[(size_t)v * CC * NN + (size_t)(c0 + r) * NN + n0 + tx] =
                __float2bfloat16_rn(tt[tx][r]);
        }
        return;
    }
    b -= SF_N;
    if (b < WR_N) {
        int c0 = (b & 7) * 32;
        int k0 = (b >> 3) * 32;
        int tx = tid & 31, ty = tid >> 5;
        #pragma unroll
        for (int q = 0; q < 4; q++) {
            int r = ty * 4 + q;
            tt[r][tx] = W[(size_t)(k0 + r) * CC + c0 + tx];
        }
        __syncthreads();
        #pragma unroll
        for (int q = 0; q < 4; q++) {
            int r = ty * 4 + q;
            float x = tt[tx][r];
            __nv_bfloat16 h = __float2bfloat16_rn(x);
            size_t off = (size_t)(c0 + r) * CC + k0 + tx;
            g_wrT_h[off] = h;
            g_wrT_r[off] = __float2bfloat16_rn(x - __bfloat162float(h));
        }
        return;
    }
    b -= WR_N;
    {
        int op = b;
        int c = tid;
        int i = c_OPI[op], j = c_OPJ[op];
        float s = 0.0f;
        #pragma unroll
        for (int k = 0; k < 16; k++) s += T[i * 16 + k] * WT[k * CC + c];
        #pragma unroll
        for (int k = 0; k < 16; k++) s += T[j * 16 + k] * WT[(16 + k) * CC + c];
        g_relWT[op * CC + c] = s;
    }
}

// ---------------- recon bf16 MMA (3-term), grid (2, 32, VV) ----------------
__global__ void __launch_bounds__(256) recon_mma_kernel() {
    __shared__ __align__(16) char sm[2][16384];
    const int t = threadIdx.x;
    const int lane = t & 31, wid = t >> 5;
    const int m0w = (wid & 3) * 32, n0w = (wid >> 2) * 64;
    const int v = blockIdx.z;
    const int m0 = blockIdx.y * 128, n0 = blockIdx.x * 128;
    const int lrow = t >> 2, q = t & 3;
    const uint32_t sbase = smem_u32(&sm[0][0]);
    const __nv_bfloat16* Ah = g_dnb_h + (size_t)v * NN * CC;
    const __nv_bfloat16* Ar = g_dnb_r + (size_t)v * NN * CC;

    float acc[2][8][4];
    #pragma unroll
    for (int a = 0; a < 2; a++)
        #pragma unroll
        for (int b = 0; b < 8; b++)
            #pragma unroll
            for (int c = 0; c < 4; c++) acc[a][b][c] = 0.0f;

    uint4 ra0, ra1, rb0, rb1;
    #define R_LDG(KB) do { \
        int seg = (KB) >> 3; \
        int kk = ((KB) & 7) << 5; \
        const __nv_bfloat16* ap = (seg == 2) ? Ar : Ah; \
        const __nv_bfloat16* bp = (seg == 1) ? g_wrT_r : g_wrT_h; \
        ra0 = *(const uint4*)(ap + (size_t)(m0 + lrow) * CC + kk + q * 8); \
        ra1 = *(const uint4*)(ap + (size_t)(m0 + lrow + 64) * CC + kk + q * 8); \
        rb0 = *(const uint4*)(bp + (size_t)(n0 + lrow) * CC + kk + q * 8); \
        rb1 = *(const uint4*)(bp + (size_t)(n0 + lrow + 64) * CC + kk + q * 8); \
    } while (0)
    #define R_STS(BUF) do { \
        char* base = &sm[BUF][0]; \
        *(uint4*)(base + swz64(lrow, q)) = ra0; \
        *(uint4*)(base + swz64(lrow + 64, q)) = ra1; \
        *(uint4*)(base + 8192 + swz64(lrow, q)) = rb0; \
        *(uint4*)(base + 8192 + swz64(lrow + 64, q)) = rb1; \
    } while (0)

    R_LDG(0);
    R_STS(0);
    __syncthreads();
    for (int kb = 0; kb < 24; kb++) {
        int buf = kb & 1;
        if (kb + 1 < 24) R_LDG(kb + 1);
        mma_block(sbase + buf * 16384, sbase + buf * 16384 + 8192, lane, m0w, n0w, acc);
        if (kb + 1 < 24) R_STS(buf ^ 1);
        __syncthreads();
    }
    #undef R_LDG
    #undef R_STS

    const int gid = lane >> 2, tig = lane & 3;
    float* C = g_recon + (size_t)v * NN * CC;
    #pragma unroll
    for (int mt = 0; mt < 2; mt++) {
        int r0 = m0 + m0w + mt * 16 + gid;
        #pragma unroll
        for (int np = 0; np < 8; np++) {
            int c = n0 + n0w + np * 8 + tig * 2;
            *(float2*)&C[(size_t)r0 * CC + c] = make_float2(acc[mt][np][0], acc[mt][np][1]);
            *(float2*)&C[(size_t)(r0 + 8) * CC + c] = make_float2(acc[mt][np][2], acc[mt][np][3]);
        }
    }
}

// ---------------- sim bf16 MMA (3-term), all pairs: grid (32, 32, NP) ----------
__global__ void __launch_bounds__(256) sim_all_kernel() {
    __shared__ __align__(16) char sm[2][16384];
    __shared__ float s_rv[2][128];
    __shared__ int   s_ri[2][128];
    __shared__ float s_cv[4][128];
    __shared__ int   s_ci[4][128];

    const int t = threadIdx.x;
    const int lane = t & 31, wid = t >> 5;
    const int m0w = (wid & 3) * 32, n0w = (wid >> 2) * 64;
    const int p = blockIdx.z;
    const int m0 = blockIdx.y * 128, col0 = blockIdx.x * 128;
    const int lrow = t >> 2, q = t & 3;
    const uint32_t sbase = smem_u32(&sm[0][0]);

    const __nv_bfloat16* Ah = g_dnb_h + (size_t)c_PI[p] * NN * CC;
    const __nv_bfloat16* Ar = g_dnb_r + (size_t)c_PI[p] * NN * CC;
    const __nv_bfloat16* Bh = g_dnb_h + (size_t)c_PJ[p] * NN * CC;
    const __nv_bfloat16* Br = g_dnb_r + (size_t)c_PJ[p] * NN * CC;
    __nv_bfloat16* simp = g_simb + (size_t)p * SIMSZ;

    float acc[2][8][4];
    #pragma unroll
    for (int a = 0; a < 2; a++)
        #pragma unroll
        for (int b = 0; b < 8; b++)
            #pragma unroll
            for (int c = 0; c < 4; c++) acc[a][b][c] = 0.0f;

    uint4 ra0, ra1, rb0, rb1;
    // terms: 0: h*h, 1: h*r, 2: r*h  (rr dropped)
    #define SIM_LDG(KB) do { \
        int seg = (KB) >> 3; \
        int kk = ((KB) & 7) << 5; \
        const __nv_bfloat16* ap = (seg == 2) ? Ar : Ah; \
        const __nv_bfloat16* bp = (seg == 1) ? Br : Bh; \
        ra0 = *(const uint4*)(ap + (size_t)(m0 + lrow) * CC + kk + q * 8); \
        ra1 = *(const uint4*)(ap + (size_t)(m0 + lrow + 64) * CC + kk + q * 8); \
        rb0 = *(const uint4*)(bp + (size_t)(col0 + lrow) * CC + kk + q * 8); \
        rb1 = *(const uint4*)(bp + (size_t)(col0 + lrow + 64) * CC + kk + q * 8); \
    } while (0)
    #define SIM_STS(BUF) do { \
        char* base = &sm[BUF][0]; \
        *(uint4*)(base + swz64(lrow, q)) = ra0; \
        *(uint4*)(base + swz64(lrow + 64, q)) = ra1; \
        *(uint4*)(base + 8192 + swz64(lrow, q)) = rb0; \
        *(uint4*)(base + 8192 + swz64(lrow + 64, q)) = rb1; \
    } while (0)

    SIM_LDG(0);
    SIM_STS(0);
    __syncthreads();
    for (int kb = 0; kb < 24; kb++) {
        int buf = kb & 1;
        if (kb + 1 < 24) SIM_LDG(kb + 1);
        mma_block(sbase + buf * 16384, sbase + buf * 16384 + 8192, lane, m0w, n0w, acc);
        if (kb + 1 < 24) SIM_STS(buf ^ 1);
        __syncthreads();
    }
    #undef SIM_LDG
    #undef SIM_STS

    const int gid = lane >> 2, tig = lane & 3;
    #pragma unroll
    for (int mt = 0; mt < 2; mt++) {
        int r0 = m0 + m0w + mt * 16 + gid;
        #pragma unroll
        for (int np = 0; np < 8; np++) {
            int c = col0 + n0w + np * 8 + tig * 2;
            __nv_bfloat162 lo = __float22bfloat162_rn(make_float2(acc[mt][np][0], acc[mt][np][1]));
            __nv_bfloat162 hi = __float22bfloat162_rn(make_float2(acc[mt][np][2], acc[mt][np][3]));
            *(__nv_bfloat162*)&simp[(size_t)r0 * NN + c] = lo;
            *(__nv_bfloat162*)&simp[(size_t)(r0 + 8) * NN + c] = hi;
        }
    }
    #pragma unroll
    for (int mt = 0; mt < 2; mt++)
        #pragma unroll
        for (int h = 0; h < 2; h++) {
            float bv = -FLT_MAX; int bi = 0;
            #pragma unroll
            for (int np = 0; np < 8; np++)
                #pragma unroll
                for (int e = 0; e < 2; e++) {
                    float v = acc[mt][np][h * 2 + e];
                    int c = col0 + n0w + np * 8 + tig * 2 + e;
                    if (v > bv) { bv = v; bi = c; }
                }
            #pragma unroll
            for (int o = 1; o <= 2; o <<= 1) {
                float v2 = __shfl_xor_sync(0xffffffffu, bv, o);
                int i2 = __shfl_xor_sync(0xffffffffu, bi, o);
                if (v2 > bv || (v2 == bv && i2 < bi)) { bv = v2; bi = i2; }
            }
            if (tig == 0) {
                int rl = m0w + mt * 16 + h * 8 + gid;
                s_rv[wid >> 2][rl] = bv;
                s_ri[wid >> 2][rl] = bi;
            }
        }
    #pragma unroll
    for (int np = 0; np < 8; np++)
        #pragma unroll
        for (int e = 0; e < 2; e++) {
            float bv = -FLT_MAX; int bi = 0;
            #pragma unroll
            for (int mt = 0; mt < 2; mt++)
                #pragma unroll
                for (int h = 0; h < 2; h++) {
                    float v = acc[mt][np][h * 2 + e];
                    int r = m0 + m0w + mt * 16 + h * 8 + gid;
                    if (v > bv) { bv = v; bi = r; }
                }
            #pragma unroll
            for (int o = 4; o <= 16; o <<= 1) {
                float v2 = __shfl_xor_sync(0xffffffffu, bv, o);
                int i2 = __shfl_xor_sync(0xffffffffu, bi, o);
                if (v2 > bv || (v2 == bv && i2 < bi)) { bv = v2; bi = i2; }
            }
            if (gid == 0) {
                int cl = n0w + np * 8 + tig * 2 + e;
                s_cv[wid & 3][cl] = bv;
                s_ci[wid & 3][cl] = bi;
            }
        }
    __syncthreads();
    if (t < 128) {
        float bv = s_rv[0][t]; int bi = s_ri[0][t];
        if (s_rv[1][t] > bv || (s_rv[1][t] == bv && s_ri[1][t] < bi)) { bv = s_rv[1][t]; bi = s_ri[1][t]; }
        g_rowmax_part[(size_t)p * 32 * NN + blockIdx.x * NN + m0 + t] = bv;
        g_rowidx_part[(size_t)p * 32 * NN + blockIdx.x * NN + m0 + t] = bi;
        float cv = s_cv[0][t]; int ci = s_ci[0][t];
        #pragma unroll
        for (int w = 1; w < 4; w++) {
            if (s_cv[w][t] > cv || (s_cv[w][t] == cv && s_ci[w][t] < ci)) { cv = s_cv[w][t]; ci = s_ci[w][t]; }
        }
        g_colmax_part[(size_t)p * 32 * NN + blockIdx.y * NN + col0 + t] = cv;
        g_colidx_part[(size_t)p * 32 * NN + blockIdx.y * NN + col0 + t] = ci;
    }
}

// ---------------- max reduce, all pairs: grid (16, NP) ----------------
__global__ void __launch_bounds__(256) maxreduce_all_kernel() {
    int p = blockIdx.y;
    int n = blockIdx.x * 256 + threadIdx.x;
    size_t pb = (size_t)p * 32 * NN;
    float bm = g_rowmax_part[pb + n]; int bi = g_rowidx_part[pb + n];
    for (int s = 1; s < 32; s++) {
        float v = g_rowmax_part[pb + s * NN + n];
        int i2 = g_rowidx_part[pb + s * NN + n];
        if (v > bm || (v == bm && i2 < bi)) { bm = v; bi = i2; }
    }
    g_rowmax[p * NN + n] = bm; g_rowidx[p * NN + n] = bi;
    bm = g_colmax_part[pb + n]; bi = g_colidx_part[pb + n];
    for (int s = 1; s < 32; s++) {
        float v = g_colmax_part[pb + s * NN + n];
        int i2 = g_colidx_part[pb + s * NN + n];
        if (v > bm || (v == bm && i2 < bi)) { bm = v; bi = i2; }
    }
    g_colmax[p * NN + n] = bm; g_colidx[p * NN + n] = bi;
}

// ---------------- compaction, all pairs: grid NP ----------------
__global__ void __launch_bounds__(1024) compact_all_kernel() {
    __shared__ int tsum[1024];
    int p = blockIdx.x;
    const int* ridx = g_rowidx + p * NN;
    const int* cidx = g_colidx + p * NN;
    int* rlist = g_rowlist + p * NN;
    int* clist = g_collist + p * NN;
    int t = threadIdx.x;
    int flags[8];
    int s = 0;
    #pragma unroll
    for (int u = 0; u < 8; u++) {
        int idx = t * 8 + u;
        int f;
        if (idx < NN) { int n = idx; f = (cidx[ridx[n]] == n); }
        else          { int m = idx - NN; f = (ridx[cidx[m]] == m); }
        flags[u] = f;
        s += f;
    }
    tsum[t] = s;
    __syncthreads();
    for (int off = 1; off < 1024; off <<= 1) {
        int v = (t >= off) ? tsum[t - off] : 0;
        __syncthreads();
        tsum[t] += v;
        __syncthreads();
    }
    int rowtot = tsum[511];
    int total = tsum[1023];
    if (t == 0) { g_nsel[p * 2] = rowtot; g_nsel[p * 2 + 1] = total - rowtot; }
    int run = (t > 0) ? tsum[t - 1] : 0;
    #pragma unroll
    for (int u = 0; u < 8; u++) {
        if (flags[u]) {
            int idx = t * 8 + u;
            if (idx < NN) rlist[run] = idx;
            else          clist[run - rowtot] = idx - NN;
            run++;
        }
    }
    __syncthreads();
    int coltot = total - rowtot;
    for (int i2 = rowtot + t; i2 < NN; i2 += 1024) rlist[i2] = 0;
    for (int i2 = coltot + t; i2 < NN; i2 += 1024) clist[i2] = 0;
}

// ---------------- fused exp + sum partials: grid (64, 64, NP) -------------------
__global__ void __launch_bounds__(256) exp_all_kernel() {
    __shared__ float tile[64][65];
    __shared__ int rflag[64], cflag[64];
    __shared__ int s_any;
    const int p = blockIdx.z;
    const int m0 = blockIdx.x * 64;
    const int k0 = blockIdx.y * 64;
    const int t = threadIdx.x;
    const int l = t & 31;
    const int* ridx = g_rowidx + p * NN;
    const int* cidx = g_colidx + p * NN;
    if (t == 0) s_any = 0;
    __syncthreads();
    if (t < 64) {
        int k = k0 + t;
        int f = (cidx[ridx[k]] == k);
        rflag[t] = f;
        if (__ballot_sync(0xffffffffu, f) && l == 0) atomicOr(&s_any, 1);
    } else if (t < 128) {
        int m = m0 + t - 64;
        int f = (ridx[cidx[m]] == m);
        cflag[t - 64] = f;
        if (__ballot_sync(0xffffffffu, f) && l == 0) atomicOr(&s_any, 1);
    }
    __syncthreads();
    if (!s_any) return;

    const int r = (t >> 5) * 8 + (l >> 2);
    const int c0 = (l & 3) * 16;
    const __nv_bfloat16* simp = g_simb + (size_t)p * SIMSZ;

    float fv[16];
    {
        uint4 va = *(const uint4*)(simp + (size_t)(k0 + r) * NN + m0 + c0);
        uint4 vb = *(const uint4*)(simp + (size_t)(k0 + r) * NN + m0 + c0 + 8);
        const uint32_t* ua = (const uint32_t*)&va;
        const uint32_t* ub = (const uint32_t*)&vb;
        #pragma unroll
        for (int i = 0; i < 4; i++) {
            float2 f2 = __bfloat1622float2(*(const __nv_bfloat162*)&ua[i]);
            fv[2 * i] = f2.x; fv[2 * i + 1] = f2.y;
        }
        #pragma unroll
        for (int i = 0; i < 4; i++) {
            float2 f2 = __bfloat1622float2(*(const __nv_bfloat162*)&ub[i]);
            fv[8 + 2 * i] = f2.x; fv[9 + 2 * i] = f2.y;
        }
    }
    #pragma unroll
    for (int i = 0; i < 16; i++) tile[r][c0 + i] = fv[i];

    float s = 0.0f;
    uint32_t out[8];
    const bool fr = rflag[r];
    if (fr) {
        float rm = g_rowmax[p * NN + k0 + r];
        #pragma unroll
        for (int i = 0; i < 8; i++) {
            float e0 = fast_exp(fv[2 * i] - rm);
            float e1 = fast_exp(fv[2 * i + 1] - rm);
            s += e0 + e1;
            __nv_bfloat162 b2 = __float22bfloat162_rn(make_float2(e0, e1));
            out[i] = *(uint32_t*)&b2;
        }
    }
    s += __shfl_xor_sync(0xffffffffu, s, 1);
    s += __shfl_xor_sync(0xffffffffu, s, 2);
    if (fr) {
        __nv_bfloat16* dst = g_p_h + (size_t)p * SIMSZ + (size_t)(k0 + r) * NN + m0 + c0;
        *(uint4*)dst = *(uint4*)&out[0];
        *(uint4*)(dst + 8) = *(uint4*)&out[4];
        if ((l & 3) == 0)
            g_sprow[((size_t)p * NN + k0 + r) * 64 + (m0 >> 6)] = s;
    }
    __syncthreads();

    s = 0.0f;
    const bool fc = cflag[r];
    if (fc) {
        float cm = g_colmax[p * NN + m0 + r];
        #pragma unroll
        for (int i = 0; i < 8; i++) {
            float e0 = fast_exp(tile[c0 + 2 * i][r] - cm);
            float e1 = fast_exp(tile[c0 + 2 * i + 1][r] - cm);
            s += e0 + e1;
            __nv_bfloat162 b2 = __float22bfloat162_rn(make_float2(e0, e1));
            out[i] = *(uint32_t*)&b2;
        }
    }
    s += __shfl_xor_sync(0xffffffffu, s, 1);
    s += __shfl_xor_sync(0xffffffffu, s, 2);
    if (fc) {
        __nv_bfloat16* dst = g_pT_h + (size_t)p * SIMSZ + (size_t)(m0 + r) * NN + k0 + c0;
        *(uint4*)dst = *(uint4*)&out[0];
        *(uint4*)(dst + 8) = *(uint4*)&out[4];
        if ((l & 3) == 0)
            g_spcol[((size_t)p * NN + m0 + r) * 64 + (k0 >> 6)] = s;
    }
}

// ---------------- sums: 8 slots per block, grid (NN/8, 2, NP), 256 thr -----------
__global__ void __launch_bounds__(256) sums_all_kernel() {
    int p = blockIdx.z;
    int dir = blockIdx.y;
    int w = threadIdx.x >> 5;
    int b = blockIdx.x * 8 + w;
    if (b >= g_nsel[p * 2 + dir]) return;
    int row = dir ? g_collist[p * NN + b] : g_rowlist[p * NN + b];
    const float* part = (dir ? g_spcol : g_sprow) + ((size_t)p * NN + row) * 64;
    int t = threadIdx.x & 31;
    float s = part[t] + part[t + 32];
    #pragma unroll
    for (int o = 16; o > 0; o >>= 1) s += __shfl_xor_sync(0xffffffffu, s, o);
    if (t == 0) {
        if (dir) g_colsum[p * NN + row] = s;
        else     g_rowsum[p * NN + row] = s;
    }
}

// ---------------- weighted bf16 MMA, 1-term: grid (2, 32, NP*2) ----------------
__global__ void __launch_bounds__(256) gemm_all_kernel() {
    const int p = blockIdx.z >> 1;
    const int dir = blockIdx.z & 1;
    const int m0 = blockIdx.y * 128;
    const int nsel = g_nsel[p * 2 + dir];
    if (m0 >= nsel) return;
    __shared__ __align__(16) char sm[2][16384];

    const int t = threadIdx.x;
    const int lane = t & 31, wid = t >> 5;
    const int m0w = (wid & 3) * 32, n0w = (wid >> 2) * 64;
    const int n0 = blockIdx.x * 128;
    const int lrow = t >> 2, q = t & 3;
    const uint32_t sbase = smem_u32(&sm[0][0]);

    const int* list = (dir ? g_collist : g_rowlist) + p * NN;
    const __nv_bfloat16* Ph = (dir ? g_pT_h : g_p_h) + (size_t)p * SIMSZ;
    const int sv = dir ? c_PI[p] : c_PJ[p];
    const __nv_bfloat16* Sh = g_sfT_h + (size_t)sv * CC * NN;

    const int grow0 = list[m0 + lrow];
    const int grow1 = list[m0 + lrow + 64];

    float acc[2][8][4];
    #pragma unroll
    for (int a = 0; a < 2; a++)
        #pragma unroll
        for (int b = 0; b < 8; b++)
            #pragma unroll
            for (int c = 0; c < 4; c++) acc[a][b][c] = 0.0f;

    uint4 ra0, ra1, rb0, rb1;
    #define W_LDG(KB) do { \
        int kk = (KB) * 32; \
        ra0 = *(const uint4*)(Ph + (size_t)grow0 * NN + kk + q * 8); \
        ra1 = *(const uint4*)(Ph + (size_t)grow1 * NN + kk + q * 8); \
        rb0 = *(const uint4*)(Sh + (size_t)(n0 + lrow) * NN + kk + q * 8); \
        rb1 = *(const uint4*)(Sh + (size_t)(n0 + lrow + 64) * NN + kk + q * 8); \
    } while (0)
    #define W_STS(BUF) do { \
        char* base = &sm[BUF][0]; \
        *(uint4*)(base + swz64(lrow, q)) = ra0; \
        *(uint4*)(base + swz64(lrow + 64, q)) = ra1; \
        *(uint4*)(base + 8192 + swz64(lrow, q)) = rb0; \
        *(uint4*)(base + 8192 + swz64(lrow + 64, q)) = rb1; \
    } while (0)

    W_LDG(0);
    W_STS(0);
    __syncthreads();
    for (int kb = 0; kb < 128; kb++) {
        int buf = kb & 1;
        if (kb + 1 < 128) W_LDG(kb + 1);
        mma_block(sbase + buf * 16384, sbase + buf * 16384 + 8192, lane, m0w, n0w, acc);
        if (kb + 1 < 128) W_STS(buf ^ 1);
        __syncthreads();
    }
    #undef W_LDG
    #undef W_STS

    const int gid = lane >> 2, tig = lane & 3;
    const float* sums = dir ? g_colsum : g_rowsum;
    float* soft = (dir ? g_soft_col : g_soft_row) + (size_t)p * NN * CC;
    #pragma unroll
    for (int mt = 0; mt < 2; mt++) {
        int s0 = m0 + m0w + mt * 16 + gid;
        #pragma unroll
        for (int h = 0; h < 2; h++) {
            int slot = s0 + h * 8;
            if (slot >= nsel) continue;
            int row = list[slot];
            float inv = 1.0f / sums[p * NN + row];
            #pragma unroll
            for (int np = 0; np < 8; np++) {
                int c = n0 + n0w + np * 8 + tig * 2;
                *(float2*)&soft[(size_t)row * CC + c] =
                    make_float2(acc[mt][np][h * 2] * inv, acc[mt][np][h * 2 + 1] * inv);
            }
        }
    }
}

// ---------------- loss (slot-based), all: grid (32, 2, NP) ----------------
__global__ void __launch_bounds__(256) loss_all_kernel() {
    int p = blockIdx.z;
    int dir = blockIdx.y;
    int tid = threadIdx.x;
    int b = blockIdx.x;
    int op = dir ? c_OP1[p] : c_OP0[p];
    int nsel = g_nsel[p * 2 + dir];
    int start = b * 128;
    int cnt = nsel - start;
    if (cnt > 128) cnt = 128;
    if (cnt <= 0) {
        if (tid == 0) { g_sq_part[op * 32 + b] = 0.0f; g_cnt_part[op * 32 + b] = 0; }
        return;
    }
    const int* list = (dir ? g_collist : g_rowlist) + p * NN;
    __shared__ int rows[128];
    if (tid < 128 && tid < cnt) rows[tid] = list[start + tid];
    __syncthreads();
    const float* soft = (dir ? g_soft_col : g_soft_row) + (size_t)p * NN * CC;
    const float* recon = g_recon + (size_t)(dir ? c_PJ[p] : c_PI[p]) * NN * CC;
    float relc = g_relWT[op * CC + tid];
    float lsum = 0.0f;
    for (int i = 0; i < cnt; i++) {
        int row = rows[i];
        float d = recon[(size_t)row * CC + tid] + relc - soft[(size_t)row * CC + tid];
        lsum += d * d;
    }
    __shared__ float ss[256];
    ss[tid] = lsum;
    __syncthreads();
    for (int off = 128; off > 0; off >>= 1) {
        if (tid < off) ss[tid] += ss[tid + off];
        __syncthreads();
    }
    if (tid == 0) {
        g_sq_part[op * 32 + b] = ss[0];
        g_cnt_part[op * 32 + b] = cnt;
    }
}

__global__ void finalize_kernel(float* __restrict__ out) {
    if (threadIdx.x == 0) {
        float total = 0.0f, count = 0.0f;
        for (int op = 0; op < 12; op++) {
            float sq = 0.0f;
            int cnt = 0;
            for (int b = 0; b < 32; b++) {
                sq += g_sq_part[op * 32 + b];
                cnt += g_cnt_part[op * 32 + b];
            }
            if (cnt > 0) {
                total += sq / fmaxf((float)cnt * (float)CC, 1.0f);
                count += 1.0f;
            }
        }
        out[0] = (count > 0.0f) ? (total / fmaxf(count, 1.0f)) : 0.0f;
    }
}

// ---------------- host launch ----------------
extern "C" void kernel_launch(void* const* d_in, const int* in_sizes, int n_in,
                              void* d_out, int out_size)
{
    const float* desc  = (const float*)d_in[0];
    const float* sf    = (const float*)d_in[1];
    const float* T     = (const float*)d_in[2];
    const float* W_rec = (const float*)d_in[3];
    const float* W_T   = (const float*)d_in[4];
    float* out = (float*)d_out;

    setup_kernel<<<NORM_N + SF_N + WR_N + 12, 256>>>(desc, sf, W_rec, T, W_T);
    recon_mma_kernel<<<dim3(2, 32, VV), 256>>>();

    sim_all_kernel<<<dim3(32, 32, NP), 256>>>();
    maxreduce_all_kernel<<<dim3(16, NP), 256>>>();
    compact_all_kernel<<<NP, 1024>>>();
    exp_all_kernel<<<dim3(NN / 64, NN / 64, NP), 256>>>();
    sums_all_kernel<<<dim3(NN / 8, 2, NP), 256>>>();
    gemm_all_kernel<<<dim3(2, 32, NP * 2), 256>>>();
    loss_all_kernel<<<dim3(32, 2, NP), 256>>>();

    finalize_kernel<<<1, 32>>>(out);
}

// round 16
// speedup vs baseline: 1.3567x; 1.0541x over previous
#include <cuda_runtime.h>
#include <cuda_bf16.h>
#include <cfloat>
#include <cstddef>
#include <cstdint>

#define NN 4096
#define CC 256
#define VV 4
#define NP 6
#define SIMSZ ((size_t)NN * NN)

// ---------------- scratch (per-pair axes) ----------------
__device__ __nv_bfloat16 g_dnb_h[VV * NN * CC];
__device__ __nv_bfloat16 g_dnb_r[VV * NN * CC];
__device__ __nv_bfloat16 g_sfT_h[VV * CC * NN];
__device__ __nv_bfloat16 g_wrT_h[CC * CC];
__device__ __nv_bfloat16 g_wrT_r[CC * CC];
__device__ float g_recon[VV * NN * CC];
__device__ float g_relWT[12 * CC];
__device__ __nv_bfloat16 g_simb[NP * SIMSZ];
__device__ __nv_bfloat16 g_p_h[NP * SIMSZ];
__device__ __nv_bfloat16 g_pT_h[NP * SIMSZ];

__device__ float g_rowmax_part[NP * 32 * NN];
__device__ int   g_rowidx_part[NP * 32 * NN];
__device__ float g_colmax_part[NP * 32 * NN];
__device__ int   g_colidx_part[NP * 32 * NN];
__device__ float g_rowmax[NP * NN];
__device__ int   g_rowidx[NP * NN];
__device__ float g_colmax[NP * NN];
__device__ int   g_colidx[NP * NN];
__device__ float g_rowsum[NP * NN];
__device__ float g_colsum[NP * NN];
__device__ int   g_rowlist[NP * NN];
__device__ int   g_collist[NP * NN];
__device__ int   g_nsel[NP * 2];

__device__ float g_sprow[(size_t)NP * NN * 64];
__device__ float g_spcol[(size_t)NP * NN * 64];

__device__ float g_soft_row[NP * NN * CC];
__device__ float g_soft_col[NP * NN * CC];
__device__ float g_sq_part[12 * 32];
__device__ int   g_cnt_part[12 * 32];

__constant__ int c_OPI[12] = {0,0,0,1,1,1,2,2,2,3,3,3};
__constant__ int c_OPJ[12] = {1,2,3,0,2,3,0,1,3,0,1,2};
__constant__ int c_PI[NP]  = {0,0,0,1,1,2};
__constant__ int c_PJ[NP]  = {1,2,3,2,3,3};
__constant__ int c_OP0[NP] = {0,1,2,4,5,8};
__constant__ int c_OP1[NP] = {3,6,9,7,10,11};

// ---------------- helpers ----------------
__device__ __forceinline__ uint32_t smem_u32(const void* p) {
    uint32_t a;
    asm("{ .reg .u64 t; cvta.to.shared.u64 t, %1; cvt.u32.u64 %0, t; }" : "=r"(a) : "l"(p));
    return a;
}
__device__ __forceinline__ uint32_t swz64(int row, int kc) {
    return (uint32_t)(row * 64) + (uint32_t)(((kc ^ ((row >> 1) & 3)) & 3) << 4);
}
__device__ __forceinline__ void ldm_x4(uint32_t addr, uint32_t& r0, uint32_t& r1,
                                       uint32_t& r2, uint32_t& r3) {
    asm volatile("ldmatrix.sync.aligned.m8n8.x4.shared.b16 {%0,%1,%2,%3}, [%4];"
        : "=r"(r0), "=r"(r1), "=r"(r2), "=r"(r3) : "r"(addr));
}
__device__ __forceinline__ void mma_bf16(float* c, const uint32_t* a, uint32_t b0, uint32_t b1) {
    asm volatile("mma.sync.aligned.m16n8k16.row.col.f32.bf16.bf16.f32 "
        "{%0,%1,%2,%3}, {%4,%5,%6,%7}, {%8,%9}, {%0,%1,%2,%3};"
        : "+f"(c[0]), "+f"(c[1]), "+f"(c[2]), "+f"(c[3])
        : "r"(a[0]), "r"(a[1]), "r"(a[2]), "r"(a[3]), "r"(b0), "r"(b1));
}
__device__ __forceinline__ void cp16(uint32_t saddr, const void* gptr) {
    asm volatile("cp.async.cg.shared.global [%0], [%1], 16;"
        :: "r"(saddr), "l"(__cvta_generic_to_global(gptr)) : "memory");
}
__device__ __forceinline__ float fast_exp(float x) {
    float y = x * 1.4426950408889634f;
    float n = rintf(y);
    float f = y - n;
    float r = 0.0001540353039338f;
    r = r * f + 0.0013333558146428f;
    r = r * f + 0.0096181291076285f;
    r = r * f + 0.0555041086648216f;
    r = r * f + 0.2402265069591007f;
    r = r * f + 0.6931471805599453f;
    r = r * f + 1.0f;
    return __int_as_float(__float_as_int(r) + ((int)n << 23));
}

__device__ __forceinline__ void mma_block(uint32_t sA, uint32_t sB, int lane,
                                          int m0w, int n0w, float acc[2][8][4]) {
    const int arow = m0w + (lane & 7) + ((lane >> 3) & 1) * 8;
    const int akc  = lane >> 4;
    const int brow = n0w + (lane & 7) + (lane >> 4) * 8;
    const int bkc  = (lane >> 3) & 1;
    #pragma unroll
    for (int ks = 0; ks < 2; ks++) {
        uint32_t a[2][4];
        #pragma unroll
        for (int mt = 0; mt < 2; mt++)
            ldm_x4(sA + swz64(arow + mt * 16, ks * 2 + akc),
                   a[mt][0], a[mt][1], a[mt][2], a[mt][3]);
        #pragma unroll
        for (int np = 0; np < 4; np++) {
            uint32_t b0, b1, b2, b3;
            ldm_x4(sB + swz64(brow + np * 16, ks * 2 + bkc), b0, b1, b2, b3);
            #pragma unroll
            for (int mt = 0; mt < 2; mt++) {
                mma_bf16(acc[mt][np * 2],     a[mt], b0, b1);
                mma_bf16(acc[mt][np * 2 + 1], a[mt], b2, b3);
            }
        }
    }
}

// ---------------- fused setup: normalize | sf transpose | wr transpose | relWT ---
#define NORM_N (NN * VV)
#define SF_N   ((NN / 32) * (CC / 32) * VV)
#define WR_N   64
__global__ void __launch_bounds__(256) setup_kernel(
    const float* __restrict__ desc, const float* __restrict__ sf,
    const float* __restrict__ W, const float* __restrict__ T,
    const float* __restrict__ WT)
{
    __shared__ float ss[256];
    __shared__ float tt[32][33];
    int b = blockIdx.x;
    int tid = threadIdx.x;
    if (b < NORM_N) {
        int rv = b;
        float x = desc[(size_t)rv * CC + tid];
        ss[tid] = x * x;
        __syncthreads();
        for (int off = 128; off > 0; off >>= 1) {
            if (tid < off) ss[tid] += ss[tid + off];
            __syncthreads();
        }
        float den = fmaxf(sqrtf(ss[0]), 1e-12f);
        float y = x / den;
        int n = rv / VV, v = rv % VV;
        __nv_bfloat16 h = __float2bfloat16_rn(y);
        size_t off = (size_t)(v * NN + n) * CC + tid;
        g_dnb_h[off] = h;
        g_dnb_r[off] = __float2bfloat16_rn(y - __bfloat162float(h));
        return;
    }
    b -= NORM_N;
    if (b < SF_N) {
        int v = b >> 10;
        int rem = b & 1023;
        int n0 = (rem & 127) * 32;
        int c0 = (rem >> 7) * 32;
        int tx = tid & 31, ty = tid >> 5;
        #pragma unroll
        for (int q = 0; q < 4; q++) {
            int r = ty * 4 + q;
            tt[r][tx] = sf[(size_t)(n0 + r) * (VV * CC) + v * CC + c0 + tx];
        }
        __syncthreads();
        #pragma unroll
        for (int q = 0; q < 4; q++) {
            int r = ty * 4 + q;
            g_sfT_h[(size_t)v * CC * NN + (size_t)(c0 + r) * NN + n0 + tx] =
                __float2bfloat16_rn(tt[tx][r]);
        }
        return;
    }
    b -= SF_N;
    if (b < WR_N) {
        int c0 = (b & 7) * 32;
        int k0 = (b >> 3) * 32;
        int tx = tid & 31, ty = tid >> 5;
        #pragma unroll
        for (int q = 0; q < 4; q++) {
            int r = ty * 4 + q;
            tt[r][tx] = W[(size_t)(k0 + r) * CC + c0 + tx];
        }
        __syncthreads();
        #pragma unroll
        for (int q = 0; q < 4; q++) {
            int r = ty * 4 + q;
            float x = tt[tx][r];
            __nv_bfloat16 h = __float2bfloat16_rn(x);
            size_t off = (size_t)(c0 + r) * CC + k0 + tx;
            g_wrT_h[off] = h;
            g_wrT_r[off] = __float2bfloat16_rn(x - __bfloat162float(h));
        }
        return;
    }
    b -= WR_N;
    {
        int op = b;
        int c = tid;
        int i = c_OPI[op], j = c_OPJ[op];
        float s = 0.0f;
        #pragma unroll
        for (int k = 0; k < 16; k++) s += T[i * 16 + k] * WT[k * CC + c];
        #pragma unroll
        for (int k = 0; k < 16; k++) s += T[j * 16 + k] * WT[(16 + k) * CC + c];
        g_relWT[op * CC + c] = s;
    }
}

// ---------------- recon bf16 MMA (3-term), grid (2, 32, VV) ----------------
__global__ void __launch_bounds__(256) recon_mma_kernel() {
    __shared__ __align__(16) char sm[2][16384];
    const int t = threadIdx.x;
    const int lane = t & 31, wid = t >> 5;
    const int m0w = (wid & 3) * 32, n0w = (wid >> 2) * 64;
    const int v = blockIdx.z;
    const int m0 = blockIdx.y * 128, n0 = blockIdx.x * 128;
    const int lrow = t >> 2, q = t & 3;
    const uint32_t sbase = smem_u32(&sm[0][0]);
    const __nv_bfloat16* Ah = g_dnb_h + (size_t)v * NN * CC;
    const __nv_bfloat16* Ar = g_dnb_r + (size_t)v * NN * CC;

    float acc[2][8][4];
    #pragma unroll
    for (int a = 0; a < 2; a++)
        #pragma unroll
        for (int b = 0; b < 8; b++)
            #pragma unroll
            for (int c = 0; c < 4; c++) acc[a][b][c] = 0.0f;

    uint4 ra0, ra1, rb0, rb1;
    #define R_LDG(KB) do { \
        int seg = (KB) >> 3; \
        int kk = ((KB) & 7) << 5; \
        const __nv_bfloat16* ap = (seg == 2) ? Ar : Ah; \
        const __nv_bfloat16* bp = (seg == 1) ? g_wrT_r : g_wrT_h; \
        ra0 = *(const uint4*)(ap + (size_t)(m0 + lrow) * CC + kk + q * 8); \
        ra1 = *(const uint4*)(ap + (size_t)(m0 + lrow + 64) * CC + kk + q * 8); \
        rb0 = *(const uint4*)(bp + (size_t)(n0 + lrow) * CC + kk + q * 8); \
        rb1 = *(const uint4*)(bp + (size_t)(n0 + lrow + 64) * CC + kk + q * 8); \
    } while (0)
    #define R_STS(BUF) do { \
        char* base = &sm[BUF][0]; \
        *(uint4*)(base + swz64(lrow, q)) = ra0; \
        *(uint4*)(base + swz64(lrow + 64, q)) = ra1; \
        *(uint4*)(base + 8192 + swz64(lrow, q)) = rb0; \
        *(uint4*)(base + 8192 + swz64(lrow + 64, q)) = rb1; \
    } while (0)

    R_LDG(0);
    R_STS(0);
    __syncthreads();
    for (int kb = 0; kb < 24; kb++) {
        int buf = kb & 1;
        if (kb + 1 < 24) R_LDG(kb + 1);
        mma_block(sbase + buf * 16384, sbase + buf * 16384 + 8192, lane, m0w, n0w, acc);
        if (kb + 1 < 24) R_STS(buf ^ 1);
        __syncthreads();
    }
    #undef R_LDG
    #undef R_STS

    const int gid = lane >> 2, tig = lane & 3;
    float* C = g_recon + (size_t)v * NN * CC;
    #pragma unroll
    for (int mt = 0; mt < 2; mt++) {
        int r0 = m0 + m0w + mt * 16 + gid;
        #pragma unroll
        for (int np = 0; np < 8; np++) {
            int c = n0 + n0w + np * 8 + tig * 2;
            *(float2*)&C[(size_t)r0 * CC + c] = make_float2(acc[mt][np][0], acc[mt][np][1]);
            *(float2*)&C[(size_t)(r0 + 8) * CC + c] = make_float2(acc[mt][np][2], acc[mt][np][3]);
        }
    }
}

// ---------------- sim bf16 MMA (3-term), cp.async 3-stage: grid (32, 32, NP) ----
__global__ void __launch_bounds__(256, 2) sim_all_kernel() {
    extern __shared__ __align__(16) char dynsm[];
    __shared__ float s_rv[2][128];
    __shared__ int   s_ri[2][128];
    __shared__ float s_cv[4][128];
    __shared__ int   s_ci[4][128];

    const int t = threadIdx.x;
    const int lane = t & 31, wid = t >> 5;
    const int m0w = (wid & 3) * 32, n0w = (wid >> 2) * 64;
    const int p = blockIdx.z;
    const int m0 = blockIdx.y * 128, col0 = blockIdx.x * 128;
    const int lrow = t >> 2, q = t & 3;
    const uint32_t sbase = smem_u32(dynsm);

    const __nv_bfloat16* Ah = g_dnb_h + (size_t)c_PI[p] * NN * CC;
    const __nv_bfloat16* Ar = g_dnb_r + (size_t)c_PI[p] * NN * CC;
    const __nv_bfloat16* Bh = g_dnb_h + (size_t)c_PJ[p] * NN * CC;
    const __nv_bfloat16* Br = g_dnb_r + (size_t)c_PJ[p] * NN * CC;
    __nv_bfloat16* simp = g_simb + (size_t)p * SIMSZ;

    float acc[2][8][4];
    #pragma unroll
    for (int a = 0; a < 2; a++)
        #pragma unroll
        for (int b = 0; b < 8; b++)
            #pragma unroll
            for (int c = 0; c < 4; c++) acc[a][b][c] = 0.0f;

    // terms: 0: h*h, 1: h*r, 2: r*h  (rr dropped)
    #define SIM_CP(KB, BUF) do { \
        int seg = (KB) >> 3; \
        int kk = ((KB) & 7) << 5; \
        const __nv_bfloat16* ap = (seg == 2) ? Ar : Ah; \
        const __nv_bfloat16* bp = (seg == 1) ? Br : Bh; \
        uint32_t da = sbase + (uint32_t)(BUF) * 16384u; \
        cp16(da + swz64(lrow, q),             ap + (size_t)(m0 + lrow) * CC + kk + q * 8); \
        cp16(da + swz64(lrow + 64, q),        ap + (size_t)(m0 + lrow + 64) * CC + kk + q * 8); \
        cp16(da + 8192 + swz64(lrow, q),      bp + (size_t)(col0 + lrow) * CC + kk + q * 8); \
        cp16(da + 8192 + swz64(lrow + 64, q), bp + (size_t)(col0 + lrow + 64) * CC + kk + q * 8); \
        asm volatile("cp.async.commit_group;" ::: "memory"); \
    } while (0)

    SIM_CP(0, 0);
    SIM_CP(1, 1);
    #pragma unroll 1
    for (int kb = 0; kb < 24; kb++) {
        if (kb + 1 < 24) asm volatile("cp.async.wait_group 1;" ::: "memory");
        else             asm volatile("cp.async.wait_group 0;" ::: "memory");
        __syncthreads();
        if (kb + 2 < 24) {
            int nb = (kb + 2) % 3;
            SIM_CP(kb + 2, nb);
        }
        int buf = kb % 3;
        mma_block(sbase + buf * 16384u, sbase + buf * 16384u + 8192u, lane, m0w, n0w, acc);
    }
    #undef SIM_CP
    __syncthreads();

    const int gid = lane >> 2, tig = lane & 3;
    #pragma unroll
    for (int mt = 0; mt < 2; mt++) {
        int r0 = m0 + m0w + mt * 16 + gid;
        #pragma unroll
        for (int np = 0; np < 8; np++) {
            int c = col0 + n0w + np * 8 + tig * 2;
            __nv_bfloat162 lo = __float22bfloat162_rn(make_float2(acc[mt][np][0], acc[mt][np][1]));
            __nv_bfloat162 hi = __float22bfloat162_rn(make_float2(acc[mt][np][2], acc[mt][np][3]));
            *(__nv_bfloat162*)&simp[(size_t)r0 * NN + c] = lo;
            *(__nv_bfloat162*)&simp[(size_t)(r0 + 8) * NN + c] = hi;
        }
    }
    #pragma unroll
    for (int mt = 0; mt < 2; mt++)
        #pragma unroll
        for (int h = 0; h < 2; h++) {
            float bv = -FLT_MAX; int bi = 0;
            #pragma unroll
            for (int np = 0; np < 8; np++)
                #pragma unroll
                for (int e = 0; e < 2; e++) {
                    float v = acc[mt][np][h * 2 + e];
                    int c = col0 + n0w + np * 8 + tig * 2 + e;
                    if (v > bv) { bv = v; bi = c; }
                }
            #pragma unroll
            for (int o = 1; o <= 2; o <<= 1) {
                float v2 = __shfl_xor_sync(0xffffffffu, bv, o);
                int i2 = __shfl_xor_sync(0xffffffffu, bi, o);
                if (v2 > bv || (v2 == bv && i2 < bi)) { bv = v2; bi = i2; }
            }
            if (tig == 0) {
                int rl = m0w + mt * 16 + h * 8 + gid;
                s_rv[wid >> 2][rl] = bv;
                s_ri[wid >> 2][rl] = bi;
            }
        }
    #pragma unroll
    for (int np = 0; np < 8; np++)
        #pragma unroll
        for (int e = 0; e < 2; e++) {
            float bv = -FLT_MAX; int bi = 0;
            #pragma unroll
            for (int mt = 0; mt < 2; mt++)
                #pragma unroll
                for (int h = 0; h < 2; h++) {
                    float v = acc[mt][np][h * 2 + e];
                    int r = m0 + m0w + mt * 16 + h * 8 + gid;
                    if (v > bv) { bv = v; bi = r; }
                }
            #pragma unroll
            for (int o = 4; o <= 16; o <<= 1) {
                float v2 = __shfl_xor_sync(0xffffffffu, bv, o);
                int i2 = __shfl_xor_sync(0xffffffffu, bi, o);
                if (v2 > bv || (v2 == bv && i2 < bi)) { bv = v2; bi = i2; }
            }
            if (gid == 0) {
                int cl = n0w + np * 8 + tig * 2 + e;
                s_cv[wid & 3][cl] = bv;
                s_ci[wid & 3][cl] = bi;
            }
        }
    __syncthreads();
    if (t < 128) {
        float bv = s_rv[0][t]; int bi = s_ri[0][t];
        if (s_rv[1][t] > bv || (s_rv[1][t] == bv && s_ri[1][t] < bi)) { bv = s_rv[1][t]; bi = s_ri[1][t]; }
        g_rowmax_part[(size_t)p * 32 * NN + blockIdx.x * NN + m0 + t] = bv;
        g_rowidx_part[(size_t)p * 32 * NN + blockIdx.x * NN + m0 + t] = bi;
        float cv = s_cv[0][t]; int ci = s_ci[0][t];
        #pragma unroll
        for (int w = 1; w < 4; w++) {
            if (s_cv[w][t] > cv || (s_cv[w][t] == cv && s_ci[w][t] < ci)) { cv = s_cv[w][t]; ci = s_ci[w][t]; }
        }
        g_colmax_part[(size_t)p * 32 * NN + blockIdx.y * NN + col0 + t] = cv;
        g_colidx_part[(size_t)p * 32 * NN + blockIdx.y * NN + col0 + t] = ci;
    }
}

// ---------------- max reduce, all pairs: grid (16, NP) ----------------
__global__ void __launch_bounds__(256) maxreduce_all_kernel() {
    int p = blockIdx.y;
    int n = blockIdx.x * 256 + threadIdx.x;
    size_t pb = (size_t)p * 32 * NN;
    float bm = g_rowmax_part[pb + n]; int bi = g_rowidx_part[pb + n];
    for (int s = 1; s < 32; s++) {
        float v = g_rowmax_part[pb + s * NN + n];
        int i2 = g_rowidx_part[pb + s * NN + n];
        if (v > bm || (v == bm && i2 < bi)) { bm = v; bi = i2; }
    }
    g_rowmax[p * NN + n] = bm; g_rowidx[p * NN + n] = bi;
    bm = g_colmax_part[pb + n]; bi = g_colidx_part[pb + n];
    for (int s = 1; s < 32; s++) {
        float v = g_colmax_part[pb + s * NN + n];
        int i2 = g_colidx_part[pb + s * NN + n];
        if (v > bm || (v == bm && i2 < bi)) { bm = v; bi = i2; }
    }
    g_colmax[p * NN + n] = bm; g_colidx[p * NN + n] = bi;
}

// ---------------- compaction, all pairs: grid NP ----------------
__global__ void __launch_bounds__(1024) compact_all_kernel() {
    __shared__ int tsum[1024];
    int p = blockIdx.x;
    const int* ridx = g_rowidx + p * NN;
    const int* cidx = g_colidx + p * NN;
    int* rlist = g_rowlist + p * NN;
    int* clist = g_collist + p * NN;
    int t = threadIdx.x;
    int flags[8];
    int s = 0;
    #pragma unroll
    for (int u = 0; u < 8; u++) {
        int idx = t * 8 + u;
        int f;
        if (idx < NN) { int n = idx; f = (cidx[ridx[n]] == n); }
        else          { int m = idx - NN; f = (ridx[cidx[m]] == m); }
        flags[u] = f;
        s += f;
    }
    tsum[t] = s;
    __syncthreads();
    for (int off = 1; off < 1024; off <<= 1) {
        int v = (t >= off) ? tsum[t - off] : 0;
        __syncthreads();
        tsum[t] += v;
        __syncthreads();
    }
    int rowtot = tsum[511];
    int total = tsum[1023];
    if (t == 0) { g_nsel[p * 2] = rowtot; g_nsel[p * 2 + 1] = total - rowtot; }
    int run = (t > 0) ? tsum[t - 1] : 0;
    #pragma unroll
    for (int u = 0; u < 8; u++) {
        if (flags[u]) {
            int idx = t * 8 + u;
            if (idx < NN) rlist[run] = idx;
            else          clist[run - rowtot] = idx - NN;
            run++;
        }
    }
    __syncthreads();
    int coltot = total - rowtot;
    for (int i2 = rowtot + t; i2 < NN; i2 += 1024) rlist[i2] = 0;
    for (int i2 = coltot + t; i2 < NN; i2 += 1024) clist[i2] = 0;
}

// ---------------- fused exp + sum partials: grid (64, 64, NP) -------------------
__global__ void __launch_bounds__(256) exp_all_kernel() {
    __shared__ float tile[64][65];
    __shared__ int rflag[64], cflag[64];
    __shared__ int s_any;
    const int p = blockIdx.z;
    const int m0 = blockIdx.x * 64;
    const int k0 = blockIdx.y * 64;
    const int t = threadIdx.x;
    const int l = t & 31;
    const int* ridx = g_rowidx + p * NN;
    const int* cidx = g_colidx + p * NN;
    if (t == 0) s_any = 0;
    __syncthreads();
    if (t < 64) {
        int k = k0 + t;
        int f = (cidx[ridx[k]] == k);
        rflag[t] = f;
        if (__ballot_sync(0xffffffffu, f) && l == 0) atomicOr(&s_any, 1);
    } else if (t < 128) {
        int m = m0 + t - 64;
        int f = (ridx[cidx[m]] == m);
        cflag[t - 64] = f;
        if (__ballot_sync(0xffffffffu, f) && l == 0) atomicOr(&s_any, 1);
    }
    __syncthreads();
    if (!s_any) return;

    const int r = (t >> 5) * 8 + (l >> 2);
    const int c0 = (l & 3) * 16;
    const __nv_bfloat16* simp = g_simb + (size_t)p * SIMSZ;

    float fv[16];
    {
        uint4 va = *(const uint4*)(simp + (size_t)(k0 + r) * NN + m0 + c0);
        uint4 vb = *(const uint4*)(simp + (size_t)(k0 + r) * NN + m0 + c0 + 8);
        const uint32_t* ua = (const uint32_t*)&va;
        const uint32_t* ub = (const uint32_t*)&vb;
        #pragma unroll
        for (int i = 0; i < 4; i++) {
            float2 f2 = __bfloat1622float2(*(const __nv_bfloat162*)&ua[i]);
            fv[2 * i] = f2.x; fv[2 * i + 1] = f2.y;
        }
        #pragma unroll
        for (int i = 0; i < 4; i++) {
            float2 f2 = __bfloat1622float2(*(const __nv_bfloat162*)&ub[i]);
            fv[8 + 2 * i] = f2.x; fv[9 + 2 * i] = f2.y;
        }
    }
    #pragma unroll
    for (int i = 0; i < 16; i++) tile[r][c0 + i] = fv[i];

    float s = 0.0f;
    uint32_t out[8];
    const bool fr = rflag[r];
    if (fr) {
        float rm = g_rowmax[p * NN + k0 + r];
        #pragma unroll
        for (int i = 0; i < 8; i++) {
            float e0 = fast_exp(fv[2 * i] - rm);
            float e1 = fast_exp(fv[2 * i + 1] - rm);
            s += e0 + e1;
            __nv_bfloat162 b2 = __float22bfloat162_rn(make_float2(e0, e1));
            out[i] = *(uint32_t*)&b2;
        }
    }
    s += __shfl_xor_sync(0xffffffffu, s, 1);
    s += __shfl_xor_sync(0xffffffffu, s, 2);
    if (fr) {
        __nv_bfloat16* dst = g_p_h + (size_t)p * SIMSZ + (size_t)(k0 + r) * NN + m0 + c0;
        *(uint4*)dst = *(uint4*)&out[0];
        *(uint4*)(dst + 8) = *(uint4*)&out[4];
        if ((l & 3) == 0)
            g_sprow[((size_t)p * NN + k0 + r) * 64 + (m0 >> 6)] = s;
    }
    __syncthreads();

    s = 0.0f;
    const bool fc = cflag[r];
    if (fc) {
        float cm = g_colmax[p * NN + m0 + r];
        #pragma unroll
        for (int i = 0; i < 8; i++) {
            float e0 = fast_exp(tile[c0 + 2 * i][r] - cm);
            float e1 = fast_exp(tile[c0 + 2 * i + 1][r] - cm);
            s += e0 + e1;
            __nv_bfloat162 b2 = __float22bfloat162_rn(make_float2(e0, e1));
            out[i] = *(uint32_t*)&b2;
        }
    }
    s += __shfl_xor_sync(0xffffffffu, s, 1);
    s += __shfl_xor_sync(0xffffffffu, s, 2);
    if (fc) {
        __nv_bfloat16* dst = g_pT_h + (size_t)p * SIMSZ + (size_t)(m0 + r) * NN + k0 + c0;
        *(uint4*)dst = *(uint4*)&out[0];
        *(uint4*)(dst + 8) = *(uint4*)&out[4];
        if ((l & 3) == 0)
            g_spcol[((size_t)p * NN + m0 + r) * 64 + (k0 >> 6)] = s;
    }
}

// ---------------- sums: 8 slots per block, grid (NN/8, 2, NP), 256 thr -----------
__global__ void __launch_bounds__(256) sums_all_kernel() {
    int p = blockIdx.z;
    int dir = blockIdx.y;
    int w = threadIdx.x >> 5;
    int b = blockIdx.x * 8 + w;
    if (b >= g_nsel[p * 2 + dir]) return;
    int row = dir ? g_collist[p * NN + b] : g_rowlist[p * NN + b];
    const float* part = (dir ? g_spcol : g_sprow) + ((size_t)p * NN + row) * 64;
    int t = threadIdx.x & 31;
    float s = part[t] + part[t + 32];
    #pragma unroll
    for (int o = 16; o > 0; o >>= 1) s += __shfl_xor_sync(0xffffffffu, s, o);
    if (t == 0) {
        if (dir) g_colsum[p * NN + row] = s;
        else     g_rowsum[p * NN + row] = s;
    }
}

// ---------------- weighted bf16 MMA, 1-term: grid (2, 32, NP*2) ----------------
__global__ void __launch_bounds__(256) gemm_all_kernel() {
    const int p = blockIdx.z >> 1;
    const int dir = blockIdx.z & 1;
    const int m0 = blockIdx.y * 128;
    const int nsel = g_nsel[p * 2 + dir];
    if (m0 >= nsel) return;
    __shared__ __align__(16) char sm[2][16384];

    const int t = threadIdx.x;
    const int lane = t & 31, wid = t >> 5;
    const int m0w = (wid & 3) * 32, n0w = (wid >> 2) * 64;
    const int n0 = blockIdx.x * 128;
    const int lrow = t >> 2, q = t & 3;
    const uint32_t sbase = smem_u32(&sm[0][0]);

    const int* list = (dir ? g_collist : g_rowlist) + p * NN;
    const __nv_bfloat16* Ph = (dir ? g_pT_h : g_p_h) + (size_t)p * SIMSZ;
    const int sv = dir ? c_PI[p] : c_PJ[p];
    const __nv_bfloat16* Sh = g_sfT_h + (size_t)sv * CC * NN;

    const int grow0 = list[m0 + lrow];
    const int grow1 = list[m0 + lrow + 64];

    float acc[2][8][4];
    #pragma unroll
    for (int a = 0; a < 2; a++)
        #pragma unroll
        for (int b = 0; b < 8; b++)
            #pragma unroll
            for (int c = 0; c < 4; c++) acc[a][b][c] = 0.0f;

    uint4 ra0, ra1, rb0, rb1;
    #define W_LDG(KB) do { \
        int kk = (KB) * 32; \
        ra0 = *(const uint4*)(Ph + (size_t)grow0 * NN + kk + q * 8); \
        ra1 = *(const uint4*)(Ph + (size_t)grow1 * NN + kk + q * 8); \
        rb0 = *(const uint4*)(Sh + (size_t)(n0 + lrow) * NN + kk + q * 8); \
        rb1 = *(const uint4*)(Sh + (size_t)(n0 + lrow + 64) * NN + kk + q * 8); \
    } while (0)
    #define W_STS(BUF) do { \
        char* base = &sm[BUF][0]; \
        *(uint4*)(base + swz64(lrow, q)) = ra0; \
        *(uint4*)(base + swz64(lrow + 64, q)) = ra1; \
        *(uint4*)(base + 8192 + swz64(lrow, q)) = rb0; \
        *(uint4*)(base + 8192 + swz64(lrow + 64, q)) = rb1; \
    } while (0)

    W_LDG(0);
    W_STS(0);
    __syncthreads();
    for (int kb = 0; kb < 128; kb++) {
        int buf = kb & 1;
        if (kb + 1 < 128) W_LDG(kb + 1);
        mma_block(sbase + buf * 16384, sbase + buf * 16384 + 8192, lane, m0w, n0w, acc);
        if (kb + 1 < 128) W_STS(buf ^ 1);
        __syncthreads();
    }
    #undef W_LDG
    #undef W_STS

    const int gid = lane >> 2, tig = lane & 3;
    const float* sums = dir ? g_colsum : g_rowsum;
    float* soft = (dir ? g_soft_col : g_soft_row) + (size_t)p * NN * CC;
    #pragma unroll
    for (int mt = 0; mt < 2; mt++) {
        int s0 = m0 + m0w + mt * 16 + gid;
        #pragma unroll
        for (int h = 0; h < 2; h++) {
            int slot = s0 + h * 8;
            if (slot >= nsel) continue;
            int row = list[slot];
            float inv = 1.0f / sums[p * NN + row];
            #pragma unroll
            for (int np = 0; np < 8; np++) {
                int c = n0 + n0w + np * 8 + tig * 2;
                *(float2*)&soft[(size_t)row * CC + c] =
                    make_float2(acc[mt][np][h * 2] * inv, acc[mt][np][h * 2 + 1] * inv);
            }
        }
    }
}

// ---------------- loss (slot-based), all: grid (32, 2, NP) ----------------
__global__ void __launch_bounds__(256) loss_all_kernel() {
    int p = blockIdx.z;
    int dir = blockIdx.y;
    int tid = threadIdx.x;
    int b = blockIdx.x;
    int op = dir ? c_OP1[p] : c_OP0[p];
    int nsel = g_nsel[p * 2 + dir];
    int start = b * 128;
    int cnt = nsel - start;
    if (cnt > 128) cnt = 128;
    if (cnt <= 0) {
        if (tid == 0) { g_sq_part[op * 32 + b] = 0.0f; g_cnt_part[op * 32 + b] = 0; }
        return;
    }
    const int* list = (dir ? g_collist : g_rowlist) + p * NN;
    __shared__ int rows[128];
    if (tid < 128 && tid < cnt) rows[tid] = list[start + tid];
    __syncthreads();
    const float* soft = (dir ? g_soft_col : g_soft_row) + (size_t)p * NN * CC;
    const float* recon = g_recon + (size_t)(dir ? c_PJ[p] : c_PI[p]) * NN * CC;
    float relc = g_relWT[op * CC + tid];
    float lsum = 0.0f;
    for (int i = 0; i < cnt; i++) {
        int row = rows[i];
        float d = recon[(size_t)row * CC + tid] + relc - soft[(size_t)row * CC + tid];
        lsum += d * d;
    }
    __shared__ float ss[256];
    ss[tid] = lsum;
    __syncthreads();
    for (int off = 128; off > 0; off >>= 1) {
        if (tid < off) ss[tid] += ss[tid + off];
        __syncthreads();
    }
    if (tid == 0) {
        g_sq_part[op * 32 + b] = ss[0];
        g_cnt_part[op * 32 + b] = cnt;
    }
}

__global__ void finalize_kernel(float* __restrict__ out) {
    if (threadIdx.x == 0) {
        float total = 0.0f, count = 0.0f;
        for (int op = 0; op < 12; op++) {
            float sq = 0.0f;
            int cnt = 0;
            for (int b = 0; b < 32; b++) {
                sq += g_sq_part[op * 32 + b];
                cnt += g_cnt_part[op * 32 + b];
            }
            if (cnt > 0) {
                total += sq / fmaxf((float)cnt * (float)CC, 1.0f);
                count += 1.0f;
            }
        }
        out[0] = (count > 0.0f) ? (total / fmaxf(count, 1.0f)) : 0.0f;
    }
}

// ---------------- host launch ----------------
extern "C" void kernel_launch(void* const* d_in, const int* in_sizes, int n_in,
                              void* d_out, int out_size)
{
    const float* desc  = (const float*)d_in[0];
    const float* sf    = (const float*)d_in[1];
    const float* T     = (const float*)d_in[2];
    const float* W_rec = (const float*)d_in[3];
    const float* W_T   = (const float*)d_in[4];
    float* out = (float*)d_out;

    cudaFuncSetAttribute(sim_all_kernel, cudaFuncAttributeMaxDynamicSharedMemorySize, 49152);

    setup_kernel<<<NORM_N + SF_N + WR_N + 12, 256>>>(desc, sf, W_rec, T, W_T);
    recon_mma_kernel<<<dim3(2, 32, VV), 256>>>();

    sim_all_kernel<<<dim3(32, 32, NP), 256, 49152>>>();
    maxreduce_all_kernel<<<dim3(16, NP), 256>>>();
    compact_all_kernel<<<NP, 1024>>>();
    exp_all_kernel<<<dim3(NN / 64, NN / 64, NP), 256>>>();
    sums_all_kernel<<<dim3(NN / 8, 2, NP), 256>>>();
    gemm_all_kernel<<<dim3(2, 32, NP * 2), 256>>>();
    loss_all_kernel<<<dim3(32, 2, NP), 256>>>();

    finalize_kernel<<<1, 32>>>(out);
}

// round 17
// speedup vs baseline: 1.4590x; 1.0755x over previous
#include <cuda_runtime.h>
#include <cuda_bf16.h>
#include <cfloat>
#include <cstddef>
#include <cstdint>

#define NN 4096
#define CC 256
#define VV 4
#define NP 6
#define SIMSZ ((size_t)NN * NN)

// ---------------- scratch (per-pair axes) ----------------
__device__ __nv_bfloat16 g_dnb_h[VV * NN * CC];
__device__ __nv_bfloat16 g_dnb_r[VV * NN * CC];
__device__ __nv_bfloat16 g_sfT_h[VV * CC * NN];
__device__ __nv_bfloat16 g_wrT_h[CC * CC];
__device__ __nv_bfloat16 g_wrT_r[CC * CC];
__device__ float g_recon[VV * NN * CC];
__device__ float g_relWT[12 * CC];
__device__ __nv_bfloat16 g_simb[NP * SIMSZ];
__device__ __nv_bfloat16 g_p_h[NP * SIMSZ];
__device__ __nv_bfloat16 g_pT_h[NP * SIMSZ];

__device__ float g_rowmax_part[NP * 32 * NN];
__device__ int   g_rowidx_part[NP * 32 * NN];
__device__ float g_colmax_part[NP * 32 * NN];
__device__ int   g_colidx_part[NP * 32 * NN];
__device__ float g_rowmax[NP * NN];
__device__ int   g_rowidx[NP * NN];
__device__ float g_colmax[NP * NN];
__device__ int   g_colidx[NP * NN];
__device__ float g_rowsum[NP * NN];
__device__ float g_colsum[NP * NN];
__device__ int   g_rowlist[NP * NN];
__device__ int   g_collist[NP * NN];
__device__ int   g_nsel[NP * 2];

__device__ float g_sprow[(size_t)NP * NN * 64];
__device__ float g_spcol[(size_t)NP * NN * 64];

__device__ float g_soft_row[NP * NN * CC];
__device__ float g_soft_col[NP * NN * CC];
__device__ float g_sq_part[12 * 32];
__device__ int   g_cnt_part[12 * 32];

__constant__ int c_OPI[12] = {0,0,0,1,1,1,2,2,2,3,3,3};
__constant__ int c_OPJ[12] = {1,2,3,0,2,3,0,1,3,0,1,2};
__constant__ int c_PI[NP]  = {0,0,0,1,1,2};
__constant__ int c_PJ[NP]  = {1,2,3,2,3,3};
__constant__ int c_OP0[NP] = {0,1,2,4,5,8};
__constant__ int c_OP1[NP] = {3,6,9,7,10,11};

// ---------------- helpers ----------------
__device__ __forceinline__ uint32_t smem_u32(const void* p) {
    uint32_t a;
    asm("{ .reg .u64 t; cvta.to.shared.u64 t, %1; cvt.u32.u64 %0, t; }" : "=r"(a) : "l"(p));
    return a;
}
__device__ __forceinline__ uint32_t swz64(int row, int kc) {
    return (uint32_t)(row * 64) + (uint32_t)(((kc ^ ((row >> 1) & 3)) & 3) << 4);
}
__device__ __forceinline__ void ldm_x4(uint32_t addr, uint32_t& r0, uint32_t& r1,
                                       uint32_t& r2, uint32_t& r3) {
    asm volatile("ldmatrix.sync.aligned.m8n8.x4.shared.b16 {%0,%1,%2,%3}, [%4];"
        : "=r"(r0), "=r"(r1), "=r"(r2), "=r"(r3) : "r"(addr));
}
__device__ __forceinline__ void mma_bf16(float* c, const uint32_t* a, uint32_t b0, uint32_t b1) {
    asm volatile("mma.sync.aligned.m16n8k16.row.col.f32.bf16.bf16.f32 "
        "{%0,%1,%2,%3}, {%4,%5,%6,%7}, {%8,%9}, {%0,%1,%2,%3};"
        : "+f"(c[0]), "+f"(c[1]), "+f"(c[2]), "+f"(c[3])
        : "r"(a[0]), "r"(a[1]), "r"(a[2]), "r"(a[3]), "r"(b0), "r"(b1));
}
__device__ __forceinline__ void cp16(uint32_t saddr, const void* gptr) {
    asm volatile("cp.async.cg.shared.global [%0], [%1], 16;"
        :: "r"(saddr), "l"(__cvta_generic_to_global(gptr)) : "memory");
}
__device__ __forceinline__ float fast_exp(float x) {
    float y = x * 1.4426950408889634f;
    float n = rintf(y);
    float f = y - n;
    float r = 0.0001540353039338f;
    r = r * f + 0.0013333558146428f;
    r = r * f + 0.0096181291076285f;
    r = r * f + 0.0555041086648216f;
    r = r * f + 0.2402265069591007f;
    r = r * f + 0.6931471805599453f;
    r = r * f + 1.0f;
    return __int_as_float(__float_as_int(r) + ((int)n << 23));
}

__device__ __forceinline__ void mma_block(uint32_t sA, uint32_t sB, int lane,
                                          int m0w, int n0w, float acc[2][8][4]) {
    const int arow = m0w + (lane & 7) + ((lane >> 3) & 1) * 8;
    const int akc  = lane >> 4;
    const int brow = n0w + (lane & 7) + (lane >> 4) * 8;
    const int bkc  = (lane >> 3) & 1;
    #pragma unroll
    for (int ks = 0; ks < 2; ks++) {
        uint32_t a[2][4];
        #pragma unroll
        for (int mt = 0; mt < 2; mt++)
            ldm_x4(sA + swz64(arow + mt * 16, ks * 2 + akc),
                   a[mt][0], a[mt][1], a[mt][2], a[mt][3]);
        #pragma unroll
        for (int np = 0; np < 4; np++) {
            uint32_t b0, b1, b2, b3;
            ldm_x4(sB + swz64(brow + np * 16, ks * 2 + bkc), b0, b1, b2, b3);
            #pragma unroll
            for (int mt = 0; mt < 2; mt++) {
                mma_bf16(acc[mt][np * 2],     a[mt], b0, b1);
                mma_bf16(acc[mt][np * 2 + 1], a[mt], b2, b3);
            }
        }
    }
}

// ---------------- fused setup: normalize | sf transpose | wr transpose | relWT ---
#define NORM_N (NN * VV)
#define SF_N   ((NN / 32) * (CC / 32) * VV)
#define WR_N   64
__global__ void __launch_bounds__(256) setup_kernel(
    const float* __restrict__ desc, const float* __restrict__ sf,
    const float* __restrict__ W, const float* __restrict__ T,
    const float* __restrict__ WT)
{
    __shared__ float ss[256];
    __shared__ float tt[32][33];
    int b = blockIdx.x;
    int tid = threadIdx.x;
    if (b < NORM_N) {
        int rv = b;
        float x = desc[(size_t)rv * CC + tid];
        ss[tid] = x * x;
        __syncthreads();
        for (int off = 128; off > 0; off >>= 1) {
            if (tid < off) ss[tid] += ss[tid + off];
            __syncthreads();
        }
        float den = fmaxf(sqrtf(ss[0]), 1e-12f);
        float y = x / den;
        int n = rv / VV, v = rv % VV;
        __nv_bfloat16 h = __float2bfloat16_rn(y);
        size_t off = (size_t)(v * NN + n) * CC + tid;
        g_dnb_h[off] = h;
        g_dnb_r[off] = __float2bfloat16_rn(y - __bfloat162float(h));
        return;
    }
    b -= NORM_N;
    if (b < SF_N) {
        int v = b >> 10;
        int rem = b & 1023;
        int n0 = (rem & 127) * 32;
        int c0 = (rem >> 7) * 32;
        int tx = tid & 31, ty = tid >> 5;
        #pragma unroll
        for (int q = 0; q < 4; q++) {
            int r = ty * 4 + q;
            tt[r][tx] = sf[(size_t)(n0 + r) * (VV * CC) + v * CC + c0 + tx];
        }
        __syncthreads();
        #pragma unroll
        for (int q = 0; q < 4; q++) {
            int r = ty * 4 + q;
            g_sfT_h[(size_t)v * CC * NN + (size_t)(c0 + r) * NN + n0 + tx] =
                __float2bfloat16_rn(tt[tx][r]);
        }
        return;
    }
    b -= SF_N;
    if (b < WR_N) {
        int c0 = (b & 7) * 32;
        int k0 = (b >> 3) * 32;
        int tx = tid & 31, ty = tid >> 5;
        #pragma unroll
        for (int q = 0; q < 4; q++) {
            int r = ty * 4 + q;
            tt[r][tx] = W[(size_t)(k0 + r) * CC + c0 + tx];
        }
        __syncthreads();
        #pragma unroll
        for (int q = 0; q < 4; q++) {
            int r = ty * 4 + q;
            float x = tt[tx][r];
            __nv_bfloat16 h = __float2bfloat16_rn(x);
            size_t off = (size_t)(c0 + r) * CC + k0 + tx;
            g_wrT_h[off] = h;
            g_wrT_r[off] = __float2bfloat16_rn(x - __bfloat162float(h));
        }
        return;
    }
    b -= WR_N;
    {
        int op = b;
        int c = tid;
        int i = c_OPI[op], j = c_OPJ[op];
        float s = 0.0f;
        #pragma unroll
        for (int k = 0; k < 16; k++) s += T[i * 16 + k] * WT[k * CC + c];
        #pragma unroll
        for (int k = 0; k < 16; k++) s += T[j * 16 + k] * WT[(16 + k) * CC + c];
        g_relWT[op * CC + c] = s;
    }
}

// ---------------- recon bf16 MMA (3-term), grid (2, 32, VV) ----------------
__global__ void __launch_bounds__(256) recon_mma_kernel() {
    __shared__ __align__(16) char sm[2][16384];
    const int t = threadIdx.x;
    const int lane = t & 31, wid = t >> 5;
    const int m0w = (wid & 3) * 32, n0w = (wid >> 2) * 64;
    const int v = blockIdx.z;
    const int m0 = blockIdx.y * 128, n0 = blockIdx.x * 128;
    const int lrow = t >> 2, q = t & 3;
    const uint32_t sbase = smem_u32(&sm[0][0]);
    const __nv_bfloat16* Ah = g_dnb_h + (size_t)v * NN * CC;
    const __nv_bfloat16* Ar = g_dnb_r + (size_t)v * NN * CC;

    float acc[2][8][4];
    #pragma unroll
    for (int a = 0; a < 2; a++)
        #pragma unroll
        for (int b = 0; b < 8; b++)
            #pragma unroll
            for (int c = 0; c < 4; c++) acc[a][b][c] = 0.0f;

    uint4 ra0, ra1, rb0, rb1;
    #define R_LDG(KB) do { \
        int seg = (KB) >> 3; \
        int kk = ((KB) & 7) << 5; \
        const __nv_bfloat16* ap = (seg == 2) ? Ar : Ah; \
        const __nv_bfloat16* bp = (seg == 1) ? g_wrT_r : g_wrT_h; \
        ra0 = *(const uint4*)(ap + (size_t)(m0 + lrow) * CC + kk + q * 8); \
        ra1 = *(const uint4*)(ap + (size_t)(m0 + lrow + 64) * CC + kk + q * 8); \
        rb0 = *(const uint4*)(bp + (size_t)(n0 + lrow) * CC + kk + q * 8); \
        rb1 = *(const uint4*)(bp + (size_t)(n0 + lrow + 64) * CC + kk + q * 8); \
    } while (0)
    #define R_STS(BUF) do { \
        char* base = &sm[BUF][0]; \
        *(uint4*)(base + swz64(lrow, q)) = ra0; \
        *(uint4*)(base + swz64(lrow + 64, q)) = ra1; \
        *(uint4*)(base + 8192 + swz64(lrow, q)) = rb0; \
        *(uint4*)(base + 8192 + swz64(lrow + 64, q)) = rb1; \
    } while (0)

    R_LDG(0);
    R_STS(0);
    __syncthreads();
    for (int kb = 0; kb < 24; kb++) {
        int buf = kb & 1;
        if (kb + 1 < 24) R_LDG(kb + 1);
        mma_block(sbase + buf * 16384, sbase + buf * 16384 + 8192, lane, m0w, n0w, acc);
        if (kb + 1 < 24) R_STS(buf ^ 1);
        __syncthreads();
    }
    #undef R_LDG
    #undef R_STS

    const int gid = lane >> 2, tig = lane & 3;
    float* C = g_recon + (size_t)v * NN * CC;
    #pragma unroll
    for (int mt = 0; mt < 2; mt++) {
        int r0 = m0 + m0w + mt * 16 + gid;
        #pragma unroll
        for (int np = 0; np < 8; np++) {
            int c = n0 + n0w + np * 8 + tig * 2;
            *(float2*)&C[(size_t)r0 * CC + c] = make_float2(acc[mt][np][0], acc[mt][np][1]);
            *(float2*)&C[(size_t)(r0 + 8) * CC + c] = make_float2(acc[mt][np][2], acc[mt][np][3]);
        }
    }
}

// ---------------- sim bf16 MMA (3-term), cp.async 3-stage: grid (32, 32, NP) ----
__global__ void __launch_bounds__(256, 2) sim_all_kernel() {
    extern __shared__ __align__(16) char dynsm[];
    __shared__ float s_rv[2][128];
    __shared__ int   s_ri[2][128];
    __shared__ float s_cv[4][128];
    __shared__ int   s_ci[4][128];

    const int t = threadIdx.x;
    const int lane = t & 31, wid = t >> 5;
    const int m0w = (wid & 3) * 32, n0w = (wid >> 2) * 64;
    const int p = blockIdx.z;
    const int m0 = blockIdx.y * 128, col0 = blockIdx.x * 128;
    const int lrow = t >> 2, q = t & 3;
    const uint32_t sbase = smem_u32(dynsm);

    const __nv_bfloat16* Ah = g_dnb_h + (size_t)c_PI[p] * NN * CC;
    const __nv_bfloat16* Ar = g_dnb_r + (size_t)c_PI[p] * NN * CC;
    const __nv_bfloat16* Bh = g_dnb_h + (size_t)c_PJ[p] * NN * CC;
    const __nv_bfloat16* Br = g_dnb_r + (size_t)c_PJ[p] * NN * CC;
    __nv_bfloat16* simp = g_simb + (size_t)p * SIMSZ;

    float acc[2][8][4];
    #pragma unroll
    for (int a = 0; a < 2; a++)
        #pragma unroll
        for (int b = 0; b < 8; b++)
            #pragma unroll
            for (int c = 0; c < 4; c++) acc[a][b][c] = 0.0f;

    // terms: 0: h*h, 1: h*r, 2: r*h  (rr dropped)
    #define SIM_CP(KB, BUF) do { \
        int seg = (KB) >> 3; \
        int kk = ((KB) & 7) << 5; \
        const __nv_bfloat16* ap = (seg == 2) ? Ar : Ah; \
        const __nv_bfloat16* bp = (seg == 1) ? Br : Bh; \
        uint32_t da = sbase + (uint32_t)(BUF) * 16384u; \
        cp16(da + swz64(lrow, q),             ap + (size_t)(m0 + lrow) * CC + kk + q * 8); \
        cp16(da + swz64(lrow + 64, q),        ap + (size_t)(m0 + lrow + 64) * CC + kk + q * 8); \
        cp16(da + 8192 + swz64(lrow, q),      bp + (size_t)(col0 + lrow) * CC + kk + q * 8); \
        cp16(da + 8192 + swz64(lrow + 64, q), bp + (size_t)(col0 + lrow + 64) * CC + kk + q * 8); \
        asm volatile("cp.async.commit_group;" ::: "memory"); \
    } while (0)

    SIM_CP(0, 0);
    SIM_CP(1, 1);
    #pragma unroll 1
    for (int kb = 0; kb < 24; kb++) {
        if (kb + 1 < 24) asm volatile("cp.async.wait_group 1;" ::: "memory");
        else             asm volatile("cp.async.wait_group 0;" ::: "memory");
        __syncthreads();
        if (kb + 2 < 24) {
            int nb = (kb + 2) % 3;
            SIM_CP(kb + 2, nb);
        }
        int buf = kb % 3;
        mma_block(sbase + buf * 16384u, sbase + buf * 16384u + 8192u, lane, m0w, n0w, acc);
    }
    #undef SIM_CP
    __syncthreads();

    const int gid = lane >> 2, tig = lane & 3;
    #pragma unroll
    for (int mt = 0; mt < 2; mt++) {
        int r0 = m0 + m0w + mt * 16 + gid;
        #pragma unroll
        for (int np = 0; np < 8; np++) {
            int c = col0 + n0w + np * 8 + tig * 2;
            __nv_bfloat162 lo = __float22bfloat162_rn(make_float2(acc[mt][np][0], acc[mt][np][1]));
            __nv_bfloat162 hi = __float22bfloat162_rn(make_float2(acc[mt][np][2], acc[mt][np][3]));
            *(__nv_bfloat162*)&simp[(size_t)r0 * NN + c] = lo;
            *(__nv_bfloat162*)&simp[(size_t)(r0 + 8) * NN + c] = hi;
        }
    }
    #pragma unroll
    for (int mt = 0; mt < 2; mt++)
        #pragma unroll
        for (int h = 0; h < 2; h++) {
            float bv = -FLT_MAX; int bi = 0;
            #pragma unroll
            for (int np = 0; np < 8; np++)
                #pragma unroll
                for (int e = 0; e < 2; e++) {
                    float v = acc[mt][np][h * 2 + e];
                    int c = col0 + n0w + np * 8 + tig * 2 + e;
                    if (v > bv) { bv = v; bi = c; }
                }
            #pragma unroll
            for (int o = 1; o <= 2; o <<= 1) {
                float v2 = __shfl_xor_sync(0xffffffffu, bv, o);
                int i2 = __shfl_xor_sync(0xffffffffu, bi, o);
                if (v2 > bv || (v2 == bv && i2 < bi)) { bv = v2; bi = i2; }
            }
            if (tig == 0) {
                int rl = m0w + mt * 16 + h * 8 + gid;
                s_rv[wid >> 2][rl] = bv;
                s_ri[wid >> 2][rl] = bi;
            }
        }
    #pragma unroll
    for (int np = 0; np < 8; np++)
        #pragma unroll
        for (int e = 0; e < 2; e++) {
            float bv = -FLT_MAX; int bi = 0;
            #pragma unroll
            for (int mt = 0; mt < 2; mt++)
                #pragma unroll
                for (int h = 0; h < 2; h++) {
                    float v = acc[mt][np][h * 2 + e];
                    int r = m0 + m0w + mt * 16 + h * 8 + gid;
                    if (v > bv) { bv = v; bi = r; }
                }
            #pragma unroll
            for (int o = 4; o <= 16; o <<= 1) {
                float v2 = __shfl_xor_sync(0xffffffffu, bv, o);
                int i2 = __shfl_xor_sync(0xffffffffu, bi, o);
                if (v2 > bv || (v2 == bv && i2 < bi)) { bv = v2; bi = i2; }
            }
            if (gid == 0) {
                int cl = n0w + np * 8 + tig * 2 + e;
                s_cv[wid & 3][cl] = bv;
                s_ci[wid & 3][cl] = bi;
            }
        }
    __syncthreads();
    if (t < 128) {
        float bv = s_rv[0][t]; int bi = s_ri[0][t];
        if (s_rv[1][t] > bv || (s_rv[1][t] == bv && s_ri[1][t] < bi)) { bv = s_rv[1][t]; bi = s_ri[1][t]; }
        g_rowmax_part[(size_t)p * 32 * NN + blockIdx.x * NN + m0 + t] = bv;
        g_rowidx_part[(size_t)p * 32 * NN + blockIdx.x * NN + m0 + t] = bi;
        float cv = s_cv[0][t]; int ci = s_ci[0][t];
        #pragma unroll
        for (int w = 1; w < 4; w++) {
            if (s_cv[w][t] > cv || (s_cv[w][t] == cv && s_ci[w][t] < ci)) { cv = s_cv[w][t]; ci = s_ci[w][t]; }
        }
        g_colmax_part[(size_t)p * 32 * NN + blockIdx.y * NN + col0 + t] = cv;
        g_colidx_part[(size_t)p * 32 * NN + blockIdx.y * NN + col0 + t] = ci;
    }
}

// ---------------- max reduce, all pairs: grid (16, NP) ----------------
__global__ void __launch_bounds__(256) maxreduce_all_kernel() {
    int p = blockIdx.y;
    int n = blockIdx.x * 256 + threadIdx.x;
    size_t pb = (size_t)p * 32 * NN;
    float bm = g_rowmax_part[pb + n]; int bi = g_rowidx_part[pb + n];
    for (int s = 1; s < 32; s++) {
        float v = g_rowmax_part[pb + s * NN + n];
        int i2 = g_rowidx_part[pb + s * NN + n];
        if (v > bm || (v == bm && i2 < bi)) { bm = v; bi = i2; }
    }
    g_rowmax[p * NN + n] = bm; g_rowidx[p * NN + n] = bi;
    bm = g_colmax_part[pb + n]; bi = g_colidx_part[pb + n];
    for (int s = 1; s < 32; s++) {
        float v = g_colmax_part[pb + s * NN + n];
        int i2 = g_colidx_part[pb + s * NN + n];
        if (v > bm || (v == bm && i2 < bi)) { bm = v; bi = i2; }
    }
    g_colmax[p * NN + n] = bm; g_colidx[p * NN + n] = bi;
}

// ---------------- compaction, all pairs: grid NP ----------------
__global__ void __launch_bounds__(1024) compact_all_kernel() {
    __shared__ int tsum[1024];
    int p = blockIdx.x;
    const int* ridx = g_rowidx + p * NN;
    const int* cidx = g_colidx + p * NN;
    int* rlist = g_rowlist + p * NN;
    int* clist = g_collist + p * NN;
    int t = threadIdx.x;
    int flags[8];
    int s = 0;
    #pragma unroll
    for (int u = 0; u < 8; u++) {
        int idx = t * 8 + u;
        int f;
        if (idx < NN) { int n = idx; f = (cidx[ridx[n]] == n); }
        else          { int m = idx - NN; f = (ridx[cidx[m]] == m); }
        flags[u] = f;
        s += f;
    }
    tsum[t] = s;
    __syncthreads();
    for (int off = 1; off < 1024; off <<= 1) {
        int v = (t >= off) ? tsum[t - off] : 0;
        __syncthreads();
        tsum[t] += v;
        __syncthreads();
    }
    int rowtot = tsum[511];
    int total = tsum[1023];
    if (t == 0) { g_nsel[p * 2] = rowtot; g_nsel[p * 2 + 1] = total - rowtot; }
    int run = (t > 0) ? tsum[t - 1] : 0;
    #pragma unroll
    for (int u = 0; u < 8; u++) {
        if (flags[u]) {
            int idx = t * 8 + u;
            if (idx < NN) rlist[run] = idx;
            else          clist[run - rowtot] = idx - NN;
            run++;
        }
    }
    __syncthreads();
    int coltot = total - rowtot;
    for (int i2 = rowtot + t; i2 < NN; i2 += 1024) rlist[i2] = 0;
    for (int i2 = coltot + t; i2 < NN; i2 += 1024) clist[i2] = 0;
}

// ---------------- fused exp + sum partials: grid (64, 64, NP) -------------------
__global__ void __launch_bounds__(256) exp_all_kernel() {
    __shared__ float tile[64][65];
    __shared__ int rflag[64], cflag[64];
    __shared__ int s_any;
    const int p = blockIdx.z;
    const int m0 = blockIdx.x * 64;
    const int k0 = blockIdx.y * 64;
    const int t = threadIdx.x;
    const int l = t & 31;
    const int* ridx = g_rowidx + p * NN;
    const int* cidx = g_colidx + p * NN;
    if (t == 0) s_any = 0;
    __syncthreads();
    if (t < 64) {
        int k = k0 + t;
        int f = (cidx[ridx[k]] == k);
        rflag[t] = f;
        if (__ballot_sync(0xffffffffu, f) && l == 0) atomicOr(&s_any, 1);
    } else if (t < 128) {
        int m = m0 + t - 64;
        int f = (ridx[cidx[m]] == m);
        cflag[t - 64] = f;
        if (__ballot_sync(0xffffffffu, f) && l == 0) atomicOr(&s_any, 1);
    }
    __syncthreads();
    if (!s_any) return;

    const int r = (t >> 5) * 8 + (l >> 2);
    const int c0 = (l & 3) * 16;
    const __nv_bfloat16* simp = g_simb + (size_t)p * SIMSZ;

    float fv[16];
    {
        uint4 va = *(const uint4*)(simp + (size_t)(k0 + r) * NN + m0 + c0);
        uint4 vb = *(const uint4*)(simp + (size_t)(k0 + r) * NN + m0 + c0 + 8);
        const uint32_t* ua = (const uint32_t*)&va;
        const uint32_t* ub = (const uint32_t*)&vb;
        #pragma unroll
        for (int i = 0; i < 4; i++) {
            float2 f2 = __bfloat1622float2(*(const __nv_bfloat162*)&ua[i]);
            fv[2 * i] = f2.x; fv[2 * i + 1] = f2.y;
        }
        #pragma unroll
        for (int i = 0; i < 4; i++) {
            float2 f2 = __bfloat1622float2(*(const __nv_bfloat162*)&ub[i]);
            fv[8 + 2 * i] = f2.x; fv[9 + 2 * i] = f2.y;
        }
    }
    #pragma unroll
    for (int i = 0; i < 16; i++) tile[r][c0 + i] = fv[i];

    float s = 0.0f;
    uint32_t out[8];
    const bool fr = rflag[r];
    if (fr) {
        float rm = g_rowmax[p * NN + k0 + r];
        #pragma unroll
        for (int i = 0; i < 8; i++) {
            float e0 = fast_exp(fv[2 * i] - rm);
            float e1 = fast_exp(fv[2 * i + 1] - rm);
            s += e0 + e1;
            __nv_bfloat162 b2 = __float22bfloat162_rn(make_float2(e0, e1));
            out[i] = *(uint32_t*)&b2;
        }
    }
    s += __shfl_xor_sync(0xffffffffu, s, 1);
    s += __shfl_xor_sync(0xffffffffu, s, 2);
    if (fr) {
        __nv_bfloat16* dst = g_p_h + (size_t)p * SIMSZ + (size_t)(k0 + r) * NN + m0 + c0;
        *(uint4*)dst = *(uint4*)&out[0];
        *(uint4*)(dst + 8) = *(uint4*)&out[4];
        if ((l & 3) == 0)
            g_sprow[((size_t)p * NN + k0 + r) * 64 + (m0 >> 6)] = s;
    }
    __syncthreads();

    s = 0.0f;
    const bool fc = cflag[r];
    if (fc) {
        float cm = g_colmax[p * NN + m0 + r];
        #pragma unroll
        for (int i = 0; i < 8; i++) {
            float e0 = fast_exp(tile[c0 + 2 * i][r] - cm);
            float e1 = fast_exp(tile[c0 + 2 * i + 1][r] - cm);
            s += e0 + e1;
            __nv_bfloat162 b2 = __float22bfloat162_rn(make_float2(e0, e1));
            out[i] = *(uint32_t*)&b2;
        }
    }
    s += __shfl_xor_sync(0xffffffffu, s, 1);
    s += __shfl_xor_sync(0xffffffffu, s, 2);
    if (fc) {
        __nv_bfloat16* dst = g_pT_h + (size_t)p * SIMSZ + (size_t)(m0 + r) * NN + k0 + c0;
        *(uint4*)dst = *(uint4*)&out[0];
        *(uint4*)(dst + 8) = *(uint4*)&out[4];
        if ((l & 3) == 0)
            g_spcol[((size_t)p * NN + m0 + r) * 64 + (k0 >> 6)] = s;
    }
}

// ---------------- sums: 8 slots per block, grid (NN/8, 2, NP), 256 thr -----------
__global__ void __launch_bounds__(256) sums_all_kernel() {
    int p = blockIdx.z;
    int dir = blockIdx.y;
    int w = threadIdx.x >> 5;
    int b = blockIdx.x * 8 + w;
    if (b >= g_nsel[p * 2 + dir]) return;
    int row = dir ? g_collist[p * NN + b] : g_rowlist[p * NN + b];
    const float* part = (dir ? g_spcol : g_sprow) + ((size_t)p * NN + row) * 64;
    int t = threadIdx.x & 31;
    float s = part[t] + part[t + 32];
    #pragma unroll
    for (int o = 16; o > 0; o >>= 1) s += __shfl_xor_sync(0xffffffffu, s, o);
    if (t == 0) {
        if (dir) g_colsum[p * NN + row] = s;
        else     g_rowsum[p * NN + row] = s;
    }
}

// ---------------- weighted bf16 MMA, cp.async 3-stage: grid (2, 32, NP*2) -------
__global__ void __launch_bounds__(256, 2) gemm_all_kernel() {
    extern __shared__ __align__(16) char dynsm[];
    const int p = blockIdx.z >> 1;
    const int dir = blockIdx.z & 1;
    const int m0 = blockIdx.y * 128;
    const int nsel = g_nsel[p * 2 + dir];
    if (m0 >= nsel) return;

    const int t = threadIdx.x;
    const int lane = t & 31, wid = t >> 5;
    const int m0w = (wid & 3) * 32, n0w = (wid >> 2) * 64;
    const int n0 = blockIdx.x * 128;
    const int lrow = t >> 2, q = t & 3;
    const uint32_t sbase = smem_u32(dynsm);

    const int* list = (dir ? g_collist : g_rowlist) + p * NN;
    const __nv_bfloat16* Ph = (dir ? g_pT_h : g_p_h) + (size_t)p * SIMSZ;
    const int sv = dir ? c_PI[p] : c_PJ[p];
    const __nv_bfloat16* Sh = g_sfT_h + (size_t)sv * CC * NN;

    const int grow0 = list[m0 + lrow];
    const int grow1 = list[m0 + lrow + 64];

    float acc[2][8][4];
    #pragma unroll
    for (int a = 0; a < 2; a++)
        #pragma unroll
        for (int b = 0; b < 8; b++)
            #pragma unroll
            for (int c = 0; c < 4; c++) acc[a][b][c] = 0.0f;

    #define W_CP(KB, BUF) do { \
        int kk = (KB) * 32; \
        uint32_t da = sbase + (uint32_t)(BUF) * 16384u; \
        cp16(da + swz64(lrow, q),             Ph + (size_t)grow0 * NN + kk + q * 8); \
        cp16(da + swz64(lrow + 64, q),        Ph + (size_t)grow1 * NN + kk + q * 8); \
        cp16(da + 8192 + swz64(lrow, q),      Sh + (size_t)(n0 + lrow) * NN + kk + q * 8); \
        cp16(da + 8192 + swz64(lrow + 64, q), Sh + (size_t)(n0 + lrow + 64) * NN + kk + q * 8); \
        asm volatile("cp.async.commit_group;" ::: "memory"); \
    } while (0)

    W_CP(0, 0);
    W_CP(1, 1);
    #pragma unroll 1
    for (int kb = 0; kb < 128; kb++) {
        if (kb + 1 < 128) asm volatile("cp.async.wait_group 1;" ::: "memory");
        else              asm volatile("cp.async.wait_group 0;" ::: "memory");
        __syncthreads();
        if (kb + 2 < 128) {
            int nb = (kb + 2) % 3;
            W_CP(kb + 2, nb);
        }
        int buf = kb % 3;
        mma_block(sbase + buf * 16384u, sbase + buf * 16384u + 8192u, lane, m0w, n0w, acc);
    }
    #undef W_CP

    const int gid = lane >> 2, tig = lane & 3;
    const float* sums = dir ? g_colsum : g_rowsum;
    float* soft = (dir ? g_soft_col : g_soft_row) + (size_t)p * NN * CC;
    #pragma unroll
    for (int mt = 0; mt < 2; mt++) {
        int s0 = m0 + m0w + mt * 16 + gid;
        #pragma unroll
        for (int h = 0; h < 2; h++) {
            int slot = s0 + h * 8;
            if (slot >= nsel) continue;
            int row = list[slot];
            float inv = 1.0f / sums[p * NN + row];
            #pragma unroll
            for (int np = 0; np < 8; np++) {
                int c = n0 + n0w + np * 8 + tig * 2;
                *(float2*)&soft[(size_t)row * CC + c] =
                    make_float2(acc[mt][np][h * 2] * inv, acc[mt][np][h * 2 + 1] * inv);
            }
        }
    }
}

// ---------------- loss (slot-based), all: grid (32, 2, NP) ----------------
__global__ void __launch_bounds__(256) loss_all_kernel() {
    int p = blockIdx.z;
    int dir = blockIdx.y;
    int tid = threadIdx.x;
    int b = blockIdx.x;
    int op = dir ? c_OP1[p] : c_OP0[p];
    int nsel = g_nsel[p * 2 + dir];
    int start = b * 128;
    int cnt = nsel - start;
    if (cnt > 128) cnt = 128;
    if (cnt <= 0) {
        if (tid == 0) { g_sq_part[op * 32 + b] = 0.0f; g_cnt_part[op * 32 + b] = 0; }
        return;
    }
    const int* list = (dir ? g_collist : g_rowlist) + p * NN;
    __shared__ int rows[128];
    if (tid < 128 && tid < cnt) rows[tid] = list[start + tid];
    __syncthreads();
    const float* soft = (dir ? g_soft_col : g_soft_row) + (size_t)p * NN * CC;
    const float* recon = g_recon + (size_t)(dir ? c_PJ[p] : c_PI[p]) * NN * CC;
    float relc = g_relWT[op * CC + tid];
    float lsum = 0.0f;
    for (int i = 0; i < cnt; i++) {
        int row = rows[i];
        float d = recon[(size_t)row * CC + tid] + relc - soft[(size_t)row * CC + tid];
        lsum += d * d;
    }
    __shared__ float ss[256];
    ss[tid] = lsum;
    __syncthreads();
    for (int off = 128; off > 0; off >>= 1) {
        if (tid < off) ss[tid] += ss[tid + off];
        __syncthreads();
    }
    if (tid == 0) {
        g_sq_part[op * 32 + b] = ss[0];
        g_cnt_part[op * 32 + b] = cnt;
    }
}

__global__ void finalize_kernel(float* __restrict__ out) {
    if (threadIdx.x == 0) {
        float total = 0.0f, count = 0.0f;
        for (int op = 0; op < 12; op++) {
            float sq = 0.0f;
            int cnt = 0;
            for (int b = 0; b < 32; b++) {
                sq += g_sq_part[op * 32 + b];
                cnt += g_cnt_part[op * 32 + b];
            }
            if (cnt > 0) {
                total += sq / fmaxf((float)cnt * (float)CC, 1.0f);
                count += 1.0f;
            }
        }
        out[0] = (count > 0.0f) ? (total / fmaxf(count, 1.0f)) : 0.0f;
    }
}

// ---------------- host launch ----------------
extern "C" void kernel_launch(void* const* d_in, const int* in_sizes, int n_in,
                              void* d_out, int out_size)
{
    const float* desc  = (const float*)d_in[0];
    const float* sf    = (const float*)d_in[1];
    const float* T     = (const float*)d_in[2];
    const float* W_rec = (const float*)d_in[3];
    const float* W_T   = (const float*)d_in[4];
    float* out = (float*)d_out;

    cudaFuncSetAttribute(sim_all_kernel, cudaFuncAttributeMaxDynamicSharedMemorySize, 49152);
    cudaFuncSetAttribute(gemm_all_kernel, cudaFuncAttributeMaxDynamicSharedMemorySize, 49152);

    setup_kernel<<<NORM_N + SF_N + WR_N + 12, 256>>>(desc, sf, W_rec, T, W_T);
    recon_mma_kernel<<<dim3(2, 32, VV), 256>>>();

    sim_all_kernel<<<dim3(32, 32, NP), 256, 49152>>>();
    maxreduce_all_kernel<<<dim3(16, NP), 256>>>();
    compact_all_kernel<<<NP, 1024>>>();
    exp_all_kernel<<<dim3(NN / 64, NN / 64, NP), 256>>>();
    sums_all_kernel<<<dim3(NN / 8, 2, NP), 256>>>();
    gemm_all_kernel<<<dim3(2, 32, NP * 2), 256, 49152>>>();
    loss_all_kernel<<<dim3(32, 2, NP), 256>>>();

    finalize_kernel<<<1, 32>>>(out);
}